// round 1
// baseline (speedup 1.0000x reference)
#include <cuda_runtime.h>
#include <cuda_bf16.h>
#include <math.h>

// Problem constants
#define BATCH 16
#define DIM 256
#define NHEADS 8
#define HEAD_DIM 32
#define KEY_DIM 16
#define NTOK 1024            // 32*32
#define QKV_OUT 512
#define BN_EPS 1e-3f
#define SCALE_F 0.25f        // KEY_DIM^-0.5

// Device scratch (allocation-free rule: static __device__ arrays)
__device__ float g_qkv[BATCH * QKV_OUT * NTOK];    // 33.5 MB
__device__ float g_vattn[BATCH * DIM * NTOK];      // 16.8 MB

// ---------------------------------------------------------------------------
// K1/K4: out[b,o,n] = BN( sum_c W[o,c] * X[b,c,n] )   (K = 256, N = 1024)
// 64x64 tile per 256-thread block, 4x4 per thread.
// ---------------------------------------------------------------------------
__global__ __launch_bounds__(256) void gemm_bn_kernel(
    const float* __restrict__ X, const float* __restrict__ W,
    const float* __restrict__ gam, const float* __restrict__ bet,
    const float* __restrict__ mu, const float* __restrict__ va,
    float* __restrict__ out, int M)
{
    const int K = 256, NN = NTOK;
    int b  = blockIdx.z;
    int o0 = blockIdx.y * 64;
    int n0 = blockIdx.x * 64;

    __shared__ float As[16][68];
    __shared__ float Bs[16][68];

    int tid = threadIdx.x;
    int tx = tid & 15, ty = tid >> 4;

    float acc[4][4] = {};
    const float* Xb = X + (size_t)b * K * NN;

    for (int k0 = 0; k0 < K; k0 += 16) {
        // A tile: W[o0+oo][k0+kk], 64x16
        {
            int oo = tid >> 2;
            int kk = (tid & 3) * 4;
            float4 t = *(const float4*)&W[(o0 + oo) * K + k0 + kk];
            As[kk + 0][oo] = t.x;
            As[kk + 1][oo] = t.y;
            As[kk + 2][oo] = t.z;
            As[kk + 3][oo] = t.w;
        }
        // B tile: X[b][k0+kk][n0+nn], 16x64
        {
            int kk = tid >> 4;
            int nn = (tid & 15) * 4;
            float4 t = *(const float4*)&Xb[(k0 + kk) * NN + n0 + nn];
            *(float4*)&Bs[kk][nn] = t;
        }
        __syncthreads();
        #pragma unroll
        for (int kk = 0; kk < 16; kk++) {
            float4 a4 = *(float4*)&As[kk][ty * 4];
            float4 b4 = *(float4*)&Bs[kk][tx * 4];
            float a[4] = {a4.x, a4.y, a4.z, a4.w};
            float bb[4] = {b4.x, b4.y, b4.z, b4.w};
            #pragma unroll
            for (int i = 0; i < 4; i++)
                #pragma unroll
                for (int j = 0; j < 4; j++)
                    acc[i][j] += a[i] * bb[j];
        }
        __syncthreads();
    }

    #pragma unroll
    for (int i = 0; i < 4; i++) {
        int o = o0 + ty * 4 + i;
        float inv = gam[o] * rsqrtf(va[o] + BN_EPS);
        float sh  = bet[o] - mu[o] * inv;
        float* op = out + ((size_t)b * M + o) * NN + n0 + tx * 4;
        #pragma unroll
        for (int j = 0; j < 4; j++)
            op[j] = acc[i][j] * inv + sh;
    }
}

// ---------------------------------------------------------------------------
// K2: attention. One CTA = (b, h, 128-query tile). Online softmax over 8
// n-tiles of 128 keys. Scores kept in smem as s[n][m] (so softmax over n is
// a column walk and PV reads contiguous m).
// ---------------------------------------------------------------------------
#define SSTR 132   // padded row stride for 128-wide tiles (floats)
#define VSTR 36    // padded row stride for v (32 + 4)

// smem layout (floats):
//   s   : 128*132 = 16896
//   qs  : 16*132  =  2112
//   ks  : 16*132  =  2112
//   vs  : 128*36  =  4608
//   rmax: 128  rsum: 128  fact: 128  pred: 256
#define ATTN_SMEM_FLOATS (128*SSTR + 16*SSTR + 16*SSTR + 128*VSTR + 128*3 + 256)
#define ATTN_SMEM_BYTES  (ATTN_SMEM_FLOATS * 4)

__global__ __launch_bounds__(256, 2) void attn_kernel(
    const float* __restrict__ qkv, float* __restrict__ vattn)
{
    extern __shared__ float sm[];
    float* s    = sm;
    float* qs   = s + 128 * SSTR;
    float* ks   = qs + 16 * SSTR;
    float* vs   = ks + 16 * SSTR;
    float* rmax = vs + 128 * VSTR;
    float* rsum = rmax + 128;
    float* fact = rsum + 128;
    float* pred = fact + 128;   // [2][128] partial max / partial sum (reused)

    int tid = threadIdx.x;
    int b = blockIdx.z, h = blockIdx.y;
    int m0 = blockIdx.x * 128;

    const float* base = qkv + ((size_t)b * QKV_OUT + h * 64) * NTOK;

    // load q tile (scaled)
    for (int i = tid; i < 16 * 128; i += 256) {
        int d = i >> 7, m = i & 127;
        qs[d * SSTR + m] = base[d * NTOK + m0 + m] * SCALE_F;
    }
    if (tid < 128) { rmax[tid] = -1e30f; rsum[tid] = 0.f; }

    // PV mapping: group g handles one 64-key half; within group:
    // d = a2*8 .. a2*8+7, m = 4*l .. 4*l+3
    int grp = tid >> 7;
    int t2  = tid & 127;
    int a2  = t2 >> 5;
    int l   = t2 & 31;

    // score mapping: n rows ty*8.., m cols tx*8..
    int tx = tid & 15, ty = tid >> 4;

    // softmax mapping
    int m  = tid & 127;
    int half = tid >> 7;

    float acc[8][4];
    #pragma unroll
    for (int i = 0; i < 8; i++)
        #pragma unroll
        for (int j = 0; j < 4; j++) acc[i][j] = 0.f;

    for (int n0 = 0; n0 < NTOK; n0 += 128) {
        // load K tile
        for (int i = tid; i < 16 * 128; i += 256) {
            int d = i >> 7, n = i & 127;
            ks[d * SSTR + n] = base[(16 + d) * NTOK + n0 + n];
        }
        // load V tile transposed: vs[n][d]
        for (int i = tid; i < 32 * 128; i += 256) {
            int d = i >> 7, n = i & 127;
            vs[n * VSTR + d] = base[(32 + d) * NTOK + n0 + n];
        }
        __syncthreads();

        // ---- scores: s[n][m] = sum_d k[d][n] * q[d][m]
        float cs[8][8];
        #pragma unroll
        for (int i = 0; i < 8; i++)
            #pragma unroll
            for (int j = 0; j < 8; j++) cs[i][j] = 0.f;
        #pragma unroll
        for (int d = 0; d < 16; d++) {
            float4 k0 = *(float4*)&ks[d * SSTR + ty * 8];
            float4 k1 = *(float4*)&ks[d * SSTR + ty * 8 + 4];
            float4 q0 = *(float4*)&qs[d * SSTR + tx * 8];
            float4 q1 = *(float4*)&qs[d * SSTR + tx * 8 + 4];
            float kr[8] = {k0.x, k0.y, k0.z, k0.w, k1.x, k1.y, k1.z, k1.w};
            float qr[8] = {q0.x, q0.y, q0.z, q0.w, q1.x, q1.y, q1.z, q1.w};
            #pragma unroll
            for (int i = 0; i < 8; i++)
                #pragma unroll
                for (int j = 0; j < 8; j++)
                    cs[i][j] += kr[i] * qr[j];
        }
        #pragma unroll
        for (int i = 0; i < 8; i++) {
            float4 w0 = {cs[i][0], cs[i][1], cs[i][2], cs[i][3]};
            float4 w1 = {cs[i][4], cs[i][5], cs[i][6], cs[i][7]};
            *(float4*)&s[(ty * 8 + i) * SSTR + tx * 8]     = w0;
            *(float4*)&s[(ty * 8 + i) * SSTR + tx * 8 + 4] = w1;
        }
        __syncthreads();

        // ---- online softmax over this tile's 128 keys (axis n), per query m
        float pm = -1e30f;
        #pragma unroll 8
        for (int nn = 0; nn < 64; nn++)
            pm = fmaxf(pm, s[(half * 64 + nn) * SSTR + m]);
        pred[half * 128 + m] = pm;
        __syncthreads();
        if (tid < 128) {
            float tm = fmaxf(pred[m], pred[128 + m]);
            float om = rmax[m];
            float nm = fmaxf(om, tm);
            fact[m] = __expf(om - nm);
            rmax[m] = nm;
        }
        __syncthreads();
        float nmv = rmax[m];
        float ps = 0.f;
        #pragma unroll 8
        for (int nn = 0; nn < 64; nn++) {
            float e = __expf(s[(half * 64 + nn) * SSTR + m] - nmv);
            s[(half * 64 + nn) * SSTR + m] = e;
            ps += e;
        }
        pred[half * 128 + m] = ps;
        // rescale running accumulators by per-m factor
        float f0 = fact[4 * l + 0], f1 = fact[4 * l + 1];
        float f2 = fact[4 * l + 2], f3 = fact[4 * l + 3];
        #pragma unroll
        for (int dd = 0; dd < 8; dd++) {
            acc[dd][0] *= f0; acc[dd][1] *= f1;
            acc[dd][2] *= f2; acc[dd][3] *= f3;
        }
        __syncthreads();
        if (tid < 128)
            rsum[m] = rsum[m] * fact[m] + pred[m] + pred[128 + m];

        // ---- PV: acc[d][m] += sum_n p[n][m] * v[n][d] (group handles 64 n)
        int nb = grp * 64;
        #pragma unroll 4
        for (int n = 0; n < 64; n++) {
            int nn = nb + n;
            float4 p4 = *(float4*)&s[nn * SSTR + 4 * l];
            float4 v0 = *(float4*)&vs[nn * VSTR + a2 * 8];
            float4 v1 = *(float4*)&vs[nn * VSTR + a2 * 8 + 4];
            float vv[8] = {v0.x, v0.y, v0.z, v0.w, v1.x, v1.y, v1.z, v1.w};
            float pp[4] = {p4.x, p4.y, p4.z, p4.w};
            #pragma unroll
            for (int dd = 0; dd < 8; dd++)
                #pragma unroll
                for (int j = 0; j < 4; j++)
                    acc[dd][j] += vv[dd] * pp[j];
        }
        __syncthreads();
    }

    // merge the two n-half groups through smem (reuse s region), then write
    float* ob = s;   // [32][128]
    if (grp == 0) {
        #pragma unroll
        for (int dd = 0; dd < 8; dd++)
            #pragma unroll
            for (int j = 0; j < 4; j++)
                ob[(a2 * 8 + dd) * 128 + 4 * l + j] = acc[dd][j];
    }
    __syncthreads();
    if (grp == 1) {
        #pragma unroll
        for (int dd = 0; dd < 8; dd++)
            #pragma unroll
            for (int j = 0; j < 4; j++)
                ob[(a2 * 8 + dd) * 128 + 4 * l + j] += acc[dd][j];
    }
    __syncthreads();

    float* outp = vattn + ((size_t)b * DIM + h * HEAD_DIM) * NTOK + m0;
    for (int i = tid; i < 32 * 128; i += 256) {
        int d = i >> 7, mm = i & 127;
        outp[d * NTOK + mm] = ob[d * 128 + mm] / rsum[mm];
    }
}

// ---------------------------------------------------------------------------
// K3: vattn += BN( dwconv3x3(v) ).  One CTA per (b, channel) 32x32 plane.
// ---------------------------------------------------------------------------
__global__ __launch_bounds__(256) void pe_add_kernel(
    const float* __restrict__ qkv, const float* __restrict__ pw,
    const float* __restrict__ gam, const float* __restrict__ bet,
    const float* __restrict__ mu, const float* __restrict__ va,
    float* __restrict__ vattn)
{
    int c = blockIdx.x, b = blockIdx.y;
    int h = c >> 5, d = c & 31;
    const float* vp = qkv + ((size_t)b * QKV_OUT + h * 64 + 32 + d) * NTOK;

    __shared__ float pl[34 * 34];
    int tid = threadIdx.x;
    for (int i = tid; i < 34 * 34; i += 256) pl[i] = 0.f;
    __syncthreads();
    for (int i = tid; i < 1024; i += 256) {
        int y = i >> 5, x = i & 31;
        pl[(y + 1) * 34 + x + 1] = vp[i];
    }
    __syncthreads();

    float w[9];
    #pragma unroll
    for (int j = 0; j < 9; j++) w[j] = pw[c * 9 + j];
    float inv = gam[c] * rsqrtf(va[c] + BN_EPS);
    float sh  = bet[c] - mu[c] * inv;

    float* op = vattn + ((size_t)b * DIM + c) * NTOK;
    for (int i = tid; i < 1024; i += 256) {
        int y = i >> 5, x = i & 31;
        float sacc = 0.f;
        #pragma unroll
        for (int ky = 0; ky < 3; ky++)
            #pragma unroll
            for (int kx = 0; kx < 3; kx++)
                sacc += pl[(y + ky) * 34 + (x + kx)] * w[ky * 3 + kx];
        op[i] += sacc * inv + sh;
    }
}

// ---------------------------------------------------------------------------
extern "C" void kernel_launch(void* const* d_in, const int* in_sizes, int n_in,
                              void* d_out, int out_size)
{
    const float* x        = (const float*)d_in[0];
    const float* qkv_w    = (const float*)d_in[1];
    const float* qkv_g    = (const float*)d_in[2];
    const float* qkv_b    = (const float*)d_in[3];
    const float* qkv_m    = (const float*)d_in[4];
    const float* qkv_v    = (const float*)d_in[5];
    const float* pe_w     = (const float*)d_in[6];
    const float* pe_g     = (const float*)d_in[7];
    const float* pe_b     = (const float*)d_in[8];
    const float* pe_m     = (const float*)d_in[9];
    const float* pe_v     = (const float*)d_in[10];
    const float* proj_w   = (const float*)d_in[11];
    const float* proj_g   = (const float*)d_in[12];
    const float* proj_b   = (const float*)d_in[13];
    const float* proj_m   = (const float*)d_in[14];
    const float* proj_v   = (const float*)d_in[15];
    float* out            = (float*)d_out;

    float *qkv_ptr, *vattn_ptr;
    cudaGetSymbolAddress((void**)&qkv_ptr, g_qkv);
    cudaGetSymbolAddress((void**)&vattn_ptr, g_vattn);

    cudaFuncSetAttribute(attn_kernel,
        cudaFuncAttributeMaxDynamicSharedMemorySize, ATTN_SMEM_BYTES);

    // K1: qkv = BN(conv1x1(x))
    gemm_bn_kernel<<<dim3(16, 8, BATCH), 256>>>(
        x, qkv_w, qkv_g, qkv_b, qkv_m, qkv_v, qkv_ptr, QKV_OUT);

    // K2: attention -> g_vattn
    attn_kernel<<<dim3(8, NHEADS, BATCH), 256, ATTN_SMEM_BYTES>>>(
        qkv_ptr, vattn_ptr);

    // K3: vattn += BN(dwconv3x3(v))
    pe_add_kernel<<<dim3(DIM, BATCH), 256>>>(
        qkv_ptr, pe_w, pe_g, pe_b, pe_m, pe_v, vattn_ptr);

    // K4: out = BN(conv1x1(vattn))
    gemm_bn_kernel<<<dim3(16, 4, BATCH), 256>>>(
        vattn_ptr, proj_w, proj_g, proj_b, proj_m, proj_v, out, DIM);
}

// round 2
// speedup vs baseline: 1.3366x; 1.3366x over previous
#include <cuda_runtime.h>
#include <cuda_bf16.h>
#include <math.h>
#include <stdint.h>

// Problem constants
#define BATCH 16
#define DIM 256
#define NHEADS 8
#define HEAD_DIM 32
#define KEY_DIM 16
#define NTOK 1024            // 32*32
#define QKV_OUT 512
#define BN_EPS 1e-3f
#define SCALE_F 0.25f        // KEY_DIM^-0.5

// Device scratch (allocation-free rule: static __device__ arrays)
__device__ float g_qkv[BATCH * QKV_OUT * NTOK];    // 33.5 MB
__device__ float g_vattn[BATCH * DIM * NTOK];      // 16.8 MB

// ---------------------------------------------------------------------------
// tf32 helpers
// ---------------------------------------------------------------------------
__device__ __forceinline__ float tf32r(float x) {
    uint32_t u;
    asm("cvt.rna.tf32.f32 %0, %1;" : "=r"(u) : "f"(x));
    return __uint_as_float(u);
}

__device__ __forceinline__ void mma_tf32(
    float& d0, float& d1, float& d2, float& d3,
    uint32_t a0, uint32_t a1, uint32_t a2, uint32_t a3,
    uint32_t b0, uint32_t b1)
{
    asm volatile(
        "mma.sync.aligned.m16n8k8.row.col.f32.tf32.tf32.f32 "
        "{%0,%1,%2,%3}, {%4,%5,%6,%7}, {%8,%9}, {%0,%1,%2,%3};"
        : "+f"(d0), "+f"(d1), "+f"(d2), "+f"(d3)
        : "r"(a0), "r"(a1), "r"(a2), "r"(a3), "r"(b0), "r"(b1));
}

// ---------------------------------------------------------------------------
// K1/K4: out[b,o,n] = BN( sum_c W[o,c] * X[b,c,n] )   (K = 256, N = 1024)
// 64x64 tile per 256-thread block, 4x4 per thread. (fp32, unchanged)
// ---------------------------------------------------------------------------
__global__ __launch_bounds__(256) void gemm_bn_kernel(
    const float* __restrict__ X, const float* __restrict__ W,
    const float* __restrict__ gam, const float* __restrict__ bet,
    const float* __restrict__ mu, const float* __restrict__ va,
    float* __restrict__ out, int M)
{
    const int K = 256, NN = NTOK;
    int b  = blockIdx.z;
    int o0 = blockIdx.y * 64;
    int n0 = blockIdx.x * 64;

    __shared__ float As[16][68];
    __shared__ float Bs[16][68];

    int tid = threadIdx.x;
    int tx = tid & 15, ty = tid >> 4;

    float acc[4][4] = {};
    const float* Xb = X + (size_t)b * K * NN;

    for (int k0 = 0; k0 < K; k0 += 16) {
        {
            int oo = tid >> 2;
            int kk = (tid & 3) * 4;
            float4 t = *(const float4*)&W[(o0 + oo) * K + k0 + kk];
            As[kk + 0][oo] = t.x;
            As[kk + 1][oo] = t.y;
            As[kk + 2][oo] = t.z;
            As[kk + 3][oo] = t.w;
        }
        {
            int kk = tid >> 4;
            int nn = (tid & 15) * 4;
            float4 t = *(const float4*)&Xb[(k0 + kk) * NN + n0 + nn];
            *(float4*)&Bs[kk][nn] = t;
        }
        __syncthreads();
        #pragma unroll
        for (int kk = 0; kk < 16; kk++) {
            float4 a4 = *(float4*)&As[kk][ty * 4];
            float4 b4 = *(float4*)&Bs[kk][tx * 4];
            float a[4] = {a4.x, a4.y, a4.z, a4.w};
            float bb[4] = {b4.x, b4.y, b4.z, b4.w};
            #pragma unroll
            for (int i = 0; i < 4; i++)
                #pragma unroll
                for (int j = 0; j < 4; j++)
                    acc[i][j] += a[i] * bb[j];
        }
        __syncthreads();
    }

    #pragma unroll
    for (int i = 0; i < 4; i++) {
        int o = o0 + ty * 4 + i;
        float inv = gam[o] * rsqrtf(va[o] + BN_EPS);
        float sh  = bet[o] - mu[o] * inv;
        float* op = out + ((size_t)b * M + o) * NN + n0 + tx * 4;
        #pragma unroll
        for (int j = 0; j < 4; j++)
            op[j] = acc[i][j] * inv + sh;
    }
}

// ---------------------------------------------------------------------------
// K2: attention with tf32 mma.sync (m16n8k8). One CTA = (b, h, 128-q tile),
// 8 warps; warp w owns query rows [16w, 16w+16). Online softmax over 8
// key tiles of 128. Scores staged in smem s[m][n]; O lives in MMA fragments.
// ---------------------------------------------------------------------------
#define QSTR 20    // qs/ks row stride (floats): conflict-free frag loads
#define KSTR 20
#define VSTR 40
#define SSTR 132

// smem floats: qs 128*20, ks 128*20, vs 128*40, s 128*132, rmax/rsum/fact 128*3, pred 256
#define ATTN_SMEM_FLOATS (128*QSTR + 128*KSTR + 128*VSTR + 128*SSTR + 3*128 + 256)
#define ATTN_SMEM_BYTES  (ATTN_SMEM_FLOATS * 4)

__global__ __launch_bounds__(256, 2) void attn_kernel(
    const float* __restrict__ qkv, float* __restrict__ vattn)
{
    extern __shared__ float sm[];
    float* qs   = sm;                       // [128][QSTR] q^T (m, d), tf32, pre-scaled
    float* ks   = qs + 128 * QSTR;          // [128][KSTR] k^T (n, d), tf32
    float* vs   = ks + 128 * KSTR;          // [128][VSTR] v^T (n, d), tf32
    float* s    = vs + 128 * VSTR;          // [128][SSTR] scores/probs (m, n)
    float* rmax = s + 128 * SSTR;
    float* rsum = rmax + 128;
    float* fact = rsum + 128;
    float* pred = fact + 128;               // [2][128]

    int tid  = threadIdx.x;
    int b    = blockIdx.z, h = blockIdx.y;
    int m0   = blockIdx.x * 128;

    int warp = tid >> 5, lane = tid & 31;
    int qr = lane >> 2;                     // 0..7
    int qc = lane & 3;                      // 0..3
    int mw = warp * 16;                     // warp's m-strip base

    int m    = tid & 127;                   // softmax row owner
    int half = tid >> 7;                    // softmax column half

    const float* base = qkv + ((size_t)b * QKV_OUT + h * 64) * NTOK;

    // q tile: qs[m][d] = tf32(q * SCALE)
    for (int i = tid; i < 16 * 128; i += 256) {
        int d = i >> 7, mm = i & 127;
        qs[mm * QSTR + d] = tf32r(base[d * NTOK + m0 + mm] * SCALE_F);
    }
    if (tid < 128) { rmax[tid] = -1e30f; rsum[tid] = 0.f; }
    __syncthreads();

    // hoist q A-fragments (constant across key tiles)
    uint32_t aq[2][4];
    #pragma unroll
    for (int kk = 0; kk < 2; kk++) {
        aq[kk][0] = __float_as_uint(qs[(mw + qr)     * QSTR + kk * 8 + qc]);
        aq[kk][1] = __float_as_uint(qs[(mw + qr + 8) * QSTR + kk * 8 + qc]);
        aq[kk][2] = __float_as_uint(qs[(mw + qr)     * QSTR + kk * 8 + qc + 4]);
        aq[kk][3] = __float_as_uint(qs[(mw + qr + 8) * QSTR + kk * 8 + qc + 4]);
    }

    // O fragments: 4 d-tiles x 4 regs (rows mw+qr/mw+qr+8, cols dt*8+2qc(+1))
    float O[4][4];
    #pragma unroll
    for (int i = 0; i < 4; i++)
        #pragma unroll
        for (int j = 0; j < 4; j++) O[i][j] = 0.f;

    for (int n0 = 0; n0 < NTOK; n0 += 128) {
        __syncthreads();   // previous PV reads of s/vs complete

        // load K tile (tf32): ks[n][d]
        for (int i = tid; i < 16 * 128; i += 256) {
            int d = i >> 7, n = i & 127;
            ks[n * KSTR + d] = tf32r(base[(16 + d) * NTOK + n0 + n]);
        }
        // load V tile (tf32): vs[n][d]
        for (int i = tid; i < 32 * 128; i += 256) {
            int d = i >> 7, n = i & 127;
            vs[n * VSTR + d] = tf32r(base[(32 + d) * NTOK + n0 + n]);
        }
        __syncthreads();

        // ---- scores: S[m][n] = q[m][:] . k[n][:], K=16 (2 ksteps)
        #pragma unroll
        for (int nt = 0; nt < 16; nt++) {
            float d0 = 0.f, d1 = 0.f, d2 = 0.f, d3 = 0.f;
            #pragma unroll
            for (int kk = 0; kk < 2; kk++) {
                uint32_t b0 = __float_as_uint(ks[(nt * 8 + qr) * KSTR + kk * 8 + qc]);
                uint32_t b1 = __float_as_uint(ks[(nt * 8 + qr) * KSTR + kk * 8 + qc + 4]);
                mma_tf32(d0, d1, d2, d3,
                         aq[kk][0], aq[kk][1], aq[kk][2], aq[kk][3], b0, b1);
            }
            *(float2*)&s[(mw + qr)     * SSTR + nt * 8 + 2 * qc] = make_float2(d0, d1);
            *(float2*)&s[(mw + qr + 8) * SSTR + nt * 8 + 2 * qc] = make_float2(d2, d3);
        }
        __syncthreads();

        // ---- online softmax over this tile's 128 keys (rows of s)
        float* row = s + m * SSTR + half * 64;
        float pm = -1e30f;
        #pragma unroll
        for (int j = 0; j < 16; j++) {
            float4 v4 = *(float4*)&row[4 * j];
            pm = fmaxf(pm, fmaxf(fmaxf(v4.x, v4.y), fmaxf(v4.z, v4.w)));
        }
        pred[half * 128 + m] = pm;
        __syncthreads();
        if (tid < 128) {
            float tm = fmaxf(pred[m], pred[128 + m]);
            float om = rmax[m];
            float nm = fmaxf(om, tm);
            fact[m] = __expf(om - nm);
            rmax[m] = nm;
        }
        __syncthreads();
        float nmv = rmax[m];
        float ps = 0.f;
        #pragma unroll
        for (int j = 0; j < 16; j++) {
            float4 v4 = *(float4*)&row[4 * j];
            float e0 = __expf(v4.x - nmv);
            float e1 = __expf(v4.y - nmv);
            float e2 = __expf(v4.z - nmv);
            float e3 = __expf(v4.w - nmv);
            ps += (e0 + e1) + (e2 + e3);
            *(float4*)&row[4 * j] =
                make_float4(tf32r(e0), tf32r(e1), tf32r(e2), tf32r(e3));
        }
        pred[half * 128 + m] = ps;
        __syncthreads();
        if (tid < 128)
            rsum[m] = rsum[m] * fact[m] + pred[m] + pred[128 + m];

        // ---- PV: rescale O by fact, then O[m][d] += sum_n P[m][n] V[n][d]
        float f0 = fact[mw + qr], f1 = fact[mw + qr + 8];
        #pragma unroll
        for (int dt = 0; dt < 4; dt++) {
            O[dt][0] *= f0; O[dt][1] *= f0;
            O[dt][2] *= f1; O[dt][3] *= f1;
        }
        #pragma unroll
        for (int kk = 0; kk < 16; kk++) {
            uint32_t a0 = __float_as_uint(s[(mw + qr)     * SSTR + kk * 8 + qc]);
            uint32_t a1 = __float_as_uint(s[(mw + qr + 8) * SSTR + kk * 8 + qc]);
            uint32_t a2 = __float_as_uint(s[(mw + qr)     * SSTR + kk * 8 + qc + 4]);
            uint32_t a3 = __float_as_uint(s[(mw + qr + 8) * SSTR + kk * 8 + qc + 4]);
            #pragma unroll
            for (int dt = 0; dt < 4; dt++) {
                uint32_t b0 = __float_as_uint(vs[(kk * 8 + qc)     * VSTR + dt * 8 + qr]);
                uint32_t b1 = __float_as_uint(vs[(kk * 8 + qc + 4) * VSTR + dt * 8 + qr]);
                mma_tf32(O[dt][0], O[dt][1], O[dt][2], O[dt][3],
                         a0, a1, a2, a3, b0, b1);
            }
        }
    }
    __syncthreads();

    // 1/rsum into fact
    if (tid < 128) fact[tid] = 1.0f / rsum[tid];
    __syncthreads();

    // write O frags to ob[m][d] (overlay s), normalized
    float* ob = s;   // [128][36]
    {
        float i0 = fact[mw + qr], i1 = fact[mw + qr + 8];
        #pragma unroll
        for (int dt = 0; dt < 4; dt++) {
            *(float2*)&ob[(mw + qr)     * 36 + dt * 8 + 2 * qc] =
                make_float2(O[dt][0] * i0, O[dt][1] * i0);
            *(float2*)&ob[(mw + qr + 8) * 36 + dt * 8 + 2 * qc] =
                make_float2(O[dt][2] * i1, O[dt][3] * i1);
        }
    }
    __syncthreads();

    float* outp = vattn + ((size_t)b * DIM + h * HEAD_DIM) * NTOK + m0;
    for (int i = tid; i < 32 * 128; i += 256) {
        int d = i >> 7, mm = i & 127;
        outp[d * NTOK + mm] = ob[mm * 36 + d];
    }
}

// ---------------------------------------------------------------------------
// K3: vattn += BN( dwconv3x3(v) ).  One CTA per (b, channel) 32x32 plane.
// ---------------------------------------------------------------------------
__global__ __launch_bounds__(256) void pe_add_kernel(
    const float* __restrict__ qkv, const float* __restrict__ pw,
    const float* __restrict__ gam, const float* __restrict__ bet,
    const float* __restrict__ mu, const float* __restrict__ va,
    float* __restrict__ vattn)
{
    int c = blockIdx.x, b = blockIdx.y;
    int h = c >> 5, d = c & 31;
    const float* vp = qkv + ((size_t)b * QKV_OUT + h * 64 + 32 + d) * NTOK;

    __shared__ float pl[34 * 34];
    int tid = threadIdx.x;
    for (int i = tid; i < 34 * 34; i += 256) pl[i] = 0.f;
    __syncthreads();
    for (int i = tid; i < 1024; i += 256) {
        int y = i >> 5, x = i & 31;
        pl[(y + 1) * 34 + x + 1] = vp[i];
    }
    __syncthreads();

    float w[9];
    #pragma unroll
    for (int j = 0; j < 9; j++) w[j] = pw[c * 9 + j];
    float inv = gam[c] * rsqrtf(va[c] + BN_EPS);
    float sh  = bet[c] - mu[c] * inv;

    float* op = vattn + ((size_t)b * DIM + c) * NTOK;
    for (int i = tid; i < 1024; i += 256) {
        int y = i >> 5, x = i & 31;
        float sacc = 0.f;
        #pragma unroll
        for (int ky = 0; ky < 3; ky++)
            #pragma unroll
            for (int kx = 0; kx < 3; kx++)
                sacc += pl[(y + ky) * 34 + (x + kx)] * w[ky * 3 + kx];
        op[i] += sacc * inv + sh;
    }
}

// ---------------------------------------------------------------------------
extern "C" void kernel_launch(void* const* d_in, const int* in_sizes, int n_in,
                              void* d_out, int out_size)
{
    const float* x        = (const float*)d_in[0];
    const float* qkv_w    = (const float*)d_in[1];
    const float* qkv_g    = (const float*)d_in[2];
    const float* qkv_b    = (const float*)d_in[3];
    const float* qkv_m    = (const float*)d_in[4];
    const float* qkv_v    = (const float*)d_in[5];
    const float* pe_w     = (const float*)d_in[6];
    const float* pe_g     = (const float*)d_in[7];
    const float* pe_b     = (const float*)d_in[8];
    const float* pe_m     = (const float*)d_in[9];
    const float* pe_v     = (const float*)d_in[10];
    const float* proj_w   = (const float*)d_in[11];
    const float* proj_g   = (const float*)d_in[12];
    const float* proj_b   = (const float*)d_in[13];
    const float* proj_m   = (const float*)d_in[14];
    const float* proj_v   = (const float*)d_in[15];
    float* out            = (float*)d_out;

    float *qkv_ptr, *vattn_ptr;
    cudaGetSymbolAddress((void**)&qkv_ptr, g_qkv);
    cudaGetSymbolAddress((void**)&vattn_ptr, g_vattn);

    cudaFuncSetAttribute(attn_kernel,
        cudaFuncAttributeMaxDynamicSharedMemorySize, ATTN_SMEM_BYTES);

    // K1: qkv = BN(conv1x1(x))
    gemm_bn_kernel<<<dim3(16, 8, BATCH), 256>>>(
        x, qkv_w, qkv_g, qkv_b, qkv_m, qkv_v, qkv_ptr, QKV_OUT);

    // K2: attention -> g_vattn  (tf32 tensor-core path)
    attn_kernel<<<dim3(8, NHEADS, BATCH), 256, ATTN_SMEM_BYTES>>>(
        qkv_ptr, vattn_ptr);

    // K3: vattn += BN(dwconv3x3(v))
    pe_add_kernel<<<dim3(DIM, BATCH), 256>>>(
        qkv_ptr, pe_w, pe_g, pe_b, pe_m, pe_v, vattn_ptr);

    // K4: out = BN(conv1x1(vattn))
    gemm_bn_kernel<<<dim3(16, 4, BATCH), 256>>>(
        vattn_ptr, proj_w, proj_g, proj_b, proj_m, proj_v, out, DIM);
}

// round 4
// speedup vs baseline: 1.8864x; 1.4114x over previous
#include <cuda_runtime.h>
#include <cuda_bf16.h>
#include <math.h>
#include <stdint.h>

// Problem constants
#define BATCH 16
#define DIM 256
#define NHEADS 8
#define HEAD_DIM 32
#define KEY_DIM 16
#define NTOK 1024            // 32*32
#define QKV_OUT 512
#define BN_EPS 1e-3f
#define SCALE_F 0.25f        // KEY_DIM^-0.5
#define LOG2E 1.4426950408889634f

// Device scratch (allocation-free rule: static __device__ arrays)
__device__ float g_qkv[BATCH * QKV_OUT * NTOK];    // 33.5 MB
__device__ float g_vattn[BATCH * DIM * NTOK];      // 16.8 MB

// ---------------------------------------------------------------------------
// helpers
// ---------------------------------------------------------------------------
__device__ __forceinline__ float tf32r(float x) {
    uint32_t u;
    asm("cvt.rna.tf32.f32 %0, %1;" : "=r"(u) : "f"(x));
    return __uint_as_float(u);
}
__device__ __forceinline__ uint32_t pk2(float lo, float hi) {
    uint32_t r;  // lower half <- second source
    asm("cvt.rn.bf16x2.f32 %0, %1, %2;" : "=r"(r) : "f"(hi), "f"(lo));
    return r;
}
__device__ __forceinline__ float fex2(float x) {
    float y;
    asm("ex2.approx.ftz.f32 %0, %1;" : "=f"(y) : "f"(x));
    return y;
}
__device__ __forceinline__ void mma_tf32(
    float& d0, float& d1, float& d2, float& d3,
    uint32_t a0, uint32_t a1, uint32_t a2, uint32_t a3,
    uint32_t b0, uint32_t b1)
{
    asm volatile(
        "mma.sync.aligned.m16n8k8.row.col.f32.tf32.tf32.f32 "
        "{%0,%1,%2,%3}, {%4,%5,%6,%7}, {%8,%9}, {%0,%1,%2,%3};"
        : "+f"(d0), "+f"(d1), "+f"(d2), "+f"(d3)
        : "r"(a0), "r"(a1), "r"(a2), "r"(a3), "r"(b0), "r"(b1));
}
__device__ __forceinline__ void mma_bf16(
    float& d0, float& d1, float& d2, float& d3,
    uint32_t a0, uint32_t a1, uint32_t a2, uint32_t a3,
    uint32_t b0, uint32_t b1)
{
    asm volatile(
        "mma.sync.aligned.m16n8k16.row.col.f32.bf16.bf16.f32 "
        "{%0,%1,%2,%3}, {%4,%5,%6,%7}, {%8,%9}, {%0,%1,%2,%3};"
        : "+f"(d0), "+f"(d1), "+f"(d2), "+f"(d3)
        : "r"(a0), "r"(a1), "r"(a2), "r"(a3), "r"(b0), "r"(b1));
}

// ---------------------------------------------------------------------------
// K1/K4: out[b,o,n] = BN( sum_c W[o,c] * X[b,c,n] )   (fp32, unchanged)
// ---------------------------------------------------------------------------
__global__ __launch_bounds__(256) void gemm_bn_kernel(
    const float* __restrict__ X, const float* __restrict__ W,
    const float* __restrict__ gam, const float* __restrict__ bet,
    const float* __restrict__ mu, const float* __restrict__ va,
    float* __restrict__ out, int M)
{
    const int K = 256, NN = NTOK;
    int b  = blockIdx.z;
    int o0 = blockIdx.y * 64;
    int n0 = blockIdx.x * 64;

    __shared__ float As[16][68];
    __shared__ float Bs[16][68];

    int tid = threadIdx.x;
    int tx = tid & 15, ty = tid >> 4;

    float acc[4][4] = {};
    const float* Xb = X + (size_t)b * K * NN;

    for (int k0 = 0; k0 < K; k0 += 16) {
        {
            int oo = tid >> 2;
            int kk = (tid & 3) * 4;
            float4 t = *(const float4*)&W[(o0 + oo) * K + k0 + kk];
            As[kk + 0][oo] = t.x;
            As[kk + 1][oo] = t.y;
            As[kk + 2][oo] = t.z;
            As[kk + 3][oo] = t.w;
        }
        {
            int kk = tid >> 4;
            int nn = (tid & 15) * 4;
            float4 t = *(const float4*)&Xb[(k0 + kk) * NN + n0 + nn];
            *(float4*)&Bs[kk][nn] = t;
        }
        __syncthreads();
        #pragma unroll
        for (int kk = 0; kk < 16; kk++) {
            float4 a4 = *(float4*)&As[kk][ty * 4];
            float4 b4 = *(float4*)&Bs[kk][tx * 4];
            float a[4] = {a4.x, a4.y, a4.z, a4.w};
            float bb[4] = {b4.x, b4.y, b4.z, b4.w};
            #pragma unroll
            for (int i = 0; i < 4; i++)
                #pragma unroll
                for (int j = 0; j < 4; j++)
                    acc[i][j] += a[i] * bb[j];
        }
        __syncthreads();
    }

    #pragma unroll
    for (int i = 0; i < 4; i++) {
        int o = o0 + ty * 4 + i;
        float inv = gam[o] * rsqrtf(va[o] + BN_EPS);
        float sh  = bet[o] - mu[o] * inv;
        float* op = out + ((size_t)b * M + o) * NN + n0 + tx * 4;
        #pragma unroll
        for (int j = 0; j < 4; j++)
            op[j] = acc[i][j] * inv + sh;
    }
}

// ---------------------------------------------------------------------------
// K2: register-resident flash attention.
// One CTA = (b, h, 128-q rows), 8 warps * 16 rows. QK in tf32 (m16n8k8),
// softmax fully in registers (base-2), P packed to bf16 A-frags directly
// from QK C-frags, PV in bf16 (m16n8k16). Double-buffered K/V, 1 sync/tile.
// ---------------------------------------------------------------------------
#define QSTR 21          // q stage stride (floats)
#define KSTRW 136        // K row stride in floats  (16 rows of 128 + pad)
#define VSTRW 68         // V row stride in words (bf16x2) (128 bf16 + pad)
#define KBUF  (16 * KSTRW)            // 2176 floats
#define VBUF  (32 * VSTRW)            // 2176 words
#define BUFSZ (KBUF + VBUF)           // 4352 floats per stage

__global__ __launch_bounds__(256) void attn_kernel(
    const float* __restrict__ qkv, float* __restrict__ vattn)
{
    __shared__ float s_q[128 * QSTR];                 // 10752 B
    __shared__ __align__(16) float s_buf[2 * BUFSZ];  // 34816 B

    int tid  = threadIdx.x;
    int b    = blockIdx.z, h = blockIdx.y;
    int m0   = blockIdx.x * 128;

    int warp = tid >> 5, lane = tid & 31;
    int qr = lane >> 2;       // 0..7
    int qc = lane & 3;        // 0..3
    int mw = warp * 16;

    const float* base = qkv + ((size_t)b * QKV_OUT + h * 64) * NTOK;

    // ---- stage q (scaled by SCALE*log2e, tf32-rounded) ----
    const float qsc = SCALE_F * LOG2E;
    for (int i = tid; i < 16 * 128; i += 256) {
        int d = i >> 7, mm = i & 127;
        s_q[mm * QSTR + d] = tf32r(base[d * NTOK + m0 + mm] * qsc);
    }
    __syncthreads();

    // hoist q A-fragments
    uint32_t aq[2][4];
    #pragma unroll
    for (int kk = 0; kk < 2; kk++) {
        aq[kk][0] = __float_as_uint(s_q[(mw + qr)     * QSTR + kk * 8 + qc]);
        aq[kk][1] = __float_as_uint(s_q[(mw + qr + 8) * QSTR + kk * 8 + qc]);
        aq[kk][2] = __float_as_uint(s_q[(mw + qr)     * QSTR + kk * 8 + qc + 4]);
        aq[kk][3] = __float_as_uint(s_q[(mw + qr + 8) * QSTR + kk * 8 + qc + 4]);
    }

    // running stats (per-lane; rows mw+qr and mw+qr+8)
    float om0 = -1e30f, om1 = -1e30f;
    float rs0 = 0.f, rs1 = 0.f;     // per-lane partial sums (cols 2qc,2qc+1)
    float O[4][4];
    #pragma unroll
    for (int i = 0; i < 4; i++)
        #pragma unroll
        for (int j = 0; j < 4; j++) O[i][j] = 0.f;

    // staging registers
    float    kst[8];
    uint32_t vstg[8];

    // prefetch tile 0
    {
        #pragma unroll
        for (int j = 0; j < 2; j++) {
            int lin = tid + j * 256;
            int d = lin >> 5, n4 = (lin & 31) * 4;
            float4 t = *(const float4*)&base[(16 + d) * NTOK + n4];
            kst[4*j+0] = tf32r(t.x); kst[4*j+1] = tf32r(t.y);
            kst[4*j+2] = tf32r(t.z); kst[4*j+3] = tf32r(t.w);
        }
        #pragma unroll
        for (int j = 0; j < 4; j++) {
            int lin = tid + j * 256;
            int d = lin >> 5, n4 = (lin & 31) * 4;
            float4 t = *(const float4*)&base[(32 + d) * NTOK + n4];
            vstg[2*j]   = pk2(t.x, t.y);
            vstg[2*j+1] = pk2(t.z, t.w);
        }
    }

    for (int t = 0; t < 8; t++) {
        // commit staged tile into buffer t&1
        float*    kf = s_buf + (t & 1) * BUFSZ;
        uint32_t* vw = (uint32_t*)(kf + KBUF);
        #pragma unroll
        for (int j = 0; j < 2; j++) {
            int lin = tid + j * 256;
            int d = lin >> 5, n4 = (lin & 31) * 4;
            *(float4*)&kf[d * KSTRW + n4] =
                make_float4(kst[4*j], kst[4*j+1], kst[4*j+2], kst[4*j+3]);
        }
        #pragma unroll
        for (int j = 0; j < 4; j++) {
            int lin = tid + j * 256;
            int d = lin >> 5, n4 = (lin & 31) * 4;
            *(uint2*)&vw[d * VSTRW + (n4 >> 1)] = make_uint2(vstg[2*j], vstg[2*j+1]);
        }
        __syncthreads();

        // prefetch next tile (latency hidden behind compute below)
        if (t < 7) {
            int n0 = (t + 1) * 128;
            #pragma unroll
            for (int j = 0; j < 2; j++) {
                int lin = tid + j * 256;
                int d = lin >> 5, n4 = (lin & 31) * 4;
                float4 tt = *(const float4*)&base[(16 + d) * NTOK + n0 + n4];
                kst[4*j+0] = tf32r(tt.x); kst[4*j+1] = tf32r(tt.y);
                kst[4*j+2] = tf32r(tt.z); kst[4*j+3] = tf32r(tt.w);
            }
            #pragma unroll
            for (int j = 0; j < 4; j++) {
                int lin = tid + j * 256;
                int d = lin >> 5, n4 = (lin & 31) * 4;
                float4 tt = *(const float4*)&base[(32 + d) * NTOK + n0 + n4];
                vstg[2*j]   = pk2(tt.x, tt.y);
                vstg[2*j+1] = pk2(tt.z, tt.w);
            }
        }

        // ---- QK: S (in regs), 16 n-tiles, K=16 via 2 tf32 ksteps
        float S[16][4];
        #pragma unroll
        for (int nt = 0; nt < 16; nt++) {
            float d0 = 0.f, d1 = 0.f, d2 = 0.f, d3 = 0.f;
            #pragma unroll
            for (int kk = 0; kk < 2; kk++) {
                uint32_t b0 = __float_as_uint(kf[(kk*8 + qc)     * KSTRW + nt*8 + qr]);
                uint32_t b1 = __float_as_uint(kf[(kk*8 + qc + 4) * KSTRW + nt*8 + qr]);
                mma_tf32(d0, d1, d2, d3,
                         aq[kk][0], aq[kk][1], aq[kk][2], aq[kk][3], b0, b1);
            }
            S[nt][0] = d0; S[nt][1] = d1; S[nt][2] = d2; S[nt][3] = d3;
        }

        // ---- register softmax (base-2)
        float tm0 = -1e30f, tm1 = -1e30f;
        #pragma unroll
        for (int nt = 0; nt < 16; nt++) {
            tm0 = fmaxf(tm0, fmaxf(S[nt][0], S[nt][1]));
            tm1 = fmaxf(tm1, fmaxf(S[nt][2], S[nt][3]));
        }
        tm0 = fmaxf(tm0, __shfl_xor_sync(0xffffffffu, tm0, 1));
        tm0 = fmaxf(tm0, __shfl_xor_sync(0xffffffffu, tm0, 2));
        tm1 = fmaxf(tm1, __shfl_xor_sync(0xffffffffu, tm1, 1));
        tm1 = fmaxf(tm1, __shfl_xor_sync(0xffffffffu, tm1, 2));

        float nm0 = fmaxf(om0, tm0), nm1 = fmaxf(om1, tm1);
        float f0 = fex2(om0 - nm0),  f1 = fex2(om1 - nm1);
        om0 = nm0; om1 = nm1;

        float ps0 = 0.f, ps1 = 0.f;
        #pragma unroll
        for (int nt = 0; nt < 16; nt++) {
            float e0 = fex2(S[nt][0] - nm0);
            float e1 = fex2(S[nt][1] - nm0);
            float e2 = fex2(S[nt][2] - nm1);
            float e3 = fex2(S[nt][3] - nm1);
            S[nt][0] = e0; S[nt][1] = e1; S[nt][2] = e2; S[nt][3] = e3;
            ps0 += e0 + e1; ps1 += e2 + e3;
        }
        rs0 = rs0 * f0 + ps0;
        rs1 = rs1 * f1 + ps1;
        #pragma unroll
        for (int dt = 0; dt < 4; dt++) {
            O[dt][0] *= f0; O[dt][1] *= f0;
            O[dt][2] *= f1; O[dt][3] *= f1;
        }

        // ---- PV: pack P C-frags -> bf16 A-frags, mma with V from smem
        #pragma unroll
        for (int kt = 0; kt < 8; kt++) {
            uint32_t a0 = pk2(S[2*kt][0],   S[2*kt][1]);
            uint32_t a1 = pk2(S[2*kt][2],   S[2*kt][3]);
            uint32_t a2 = pk2(S[2*kt+1][0], S[2*kt+1][1]);
            uint32_t a3 = pk2(S[2*kt+1][2], S[2*kt+1][3]);
            #pragma unroll
            for (int dt = 0; dt < 4; dt++) {
                uint32_t b0 = vw[(dt*8 + qr) * VSTRW + kt*8 + qc];
                uint32_t b1 = vw[(dt*8 + qr) * VSTRW + kt*8 + qc + 4];
                mma_bf16(O[dt][0], O[dt][1], O[dt][2], O[dt][3],
                         a0, a1, a2, a3, b0, b1);
            }
        }
        // no sync needed: next iteration commits to the other buffer
    }
    __syncthreads();   // all PV reads done before overlaying output

    // final row sums (reduce per-lane partials)
    rs0 += __shfl_xor_sync(0xffffffffu, rs0, 1);
    rs0 += __shfl_xor_sync(0xffffffffu, rs0, 2);
    rs1 += __shfl_xor_sync(0xffffffffu, rs1, 1);
    rs1 += __shfl_xor_sync(0xffffffffu, rs1, 2);
    float inv0 = 1.0f / rs0, inv1 = 1.0f / rs1;

    // write O to smem transpose buffer ob[m][d] (stride 33, scalar stores —
    // odd stride keeps the transposed reads conflict-free; float2 here would
    // be a misaligned 8B store)
    float* ob = s_buf;   // 128*33 floats = 16896 B, fits in buffer region
    #pragma unroll
    for (int dt = 0; dt < 4; dt++) {
        ob[(mw + qr)     * 33 + dt*8 + 2*qc]     = O[dt][0] * inv0;
        ob[(mw + qr)     * 33 + dt*8 + 2*qc + 1] = O[dt][1] * inv0;
        ob[(mw + qr + 8) * 33 + dt*8 + 2*qc]     = O[dt][2] * inv1;
        ob[(mw + qr + 8) * 33 + dt*8 + 2*qc + 1] = O[dt][3] * inv1;
    }
    __syncthreads();

    float* outp = vattn + ((size_t)b * DIM + h * HEAD_DIM) * NTOK + m0;
    for (int i = tid; i < 32 * 128; i += 256) {
        int d = i >> 7, mm = i & 127;
        outp[d * NTOK + mm] = ob[mm * 33 + d];
    }
}

// ---------------------------------------------------------------------------
// K3: vattn += BN( dwconv3x3(v) ).  One CTA per (b, channel) 32x32 plane.
// ---------------------------------------------------------------------------
__global__ __launch_bounds__(256) void pe_add_kernel(
    const float* __restrict__ qkv, const float* __restrict__ pw,
    const float* __restrict__ gam, const float* __restrict__ bet,
    const float* __restrict__ mu, const float* __restrict__ va,
    float* __restrict__ vattn)
{
    int c = blockIdx.x, b = blockIdx.y;
    int h = c >> 5, d = c & 31;
    const float* vp = qkv + ((size_t)b * QKV_OUT + h * 64 + 32 + d) * NTOK;

    __shared__ float pl[34 * 34];
    int tid = threadIdx.x;
    for (int i = tid; i < 34 * 34; i += 256) pl[i] = 0.f;
    __syncthreads();
    for (int i = tid; i < 1024; i += 256) {
        int y = i >> 5, x = i & 31;
        pl[(y + 1) * 34 + x + 1] = vp[i];
    }
    __syncthreads();

    float w[9];
    #pragma unroll
    for (int j = 0; j < 9; j++) w[j] = pw[c * 9 + j];
    float inv = gam[c] * rsqrtf(va[c] + BN_EPS);
    float sh  = bet[c] - mu[c] * inv;

    float* op = vattn + ((size_t)b * DIM + c) * NTOK;
    for (int i = tid; i < 1024; i += 256) {
        int y = i >> 5, x = i & 31;
        float sacc = 0.f;
        #pragma unroll
        for (int ky = 0; ky < 3; ky++)
            #pragma unroll
            for (int kx = 0; kx < 3; kx++)
                sacc += pl[(y + ky) * 34 + (x + kx)] * w[ky * 3 + kx];
        op[i] += sacc * inv + sh;
    }
}

// ---------------------------------------------------------------------------
extern "C" void kernel_launch(void* const* d_in, const int* in_sizes, int n_in,
                              void* d_out, int out_size)
{
    const float* x        = (const float*)d_in[0];
    const float* qkv_w    = (const float*)d_in[1];
    const float* qkv_g    = (const float*)d_in[2];
    const float* qkv_b    = (const float*)d_in[3];
    const float* qkv_m    = (const float*)d_in[4];
    const float* qkv_v    = (const float*)d_in[5];
    const float* pe_w     = (const float*)d_in[6];
    const float* pe_g     = (const float*)d_in[7];
    const float* pe_b     = (const float*)d_in[8];
    const float* pe_m     = (const float*)d_in[9];
    const float* pe_v     = (const float*)d_in[10];
    const float* proj_w   = (const float*)d_in[11];
    const float* proj_g   = (const float*)d_in[12];
    const float* proj_b   = (const float*)d_in[13];
    const float* proj_m   = (const float*)d_in[14];
    const float* proj_v   = (const float*)d_in[15];
    float* out            = (float*)d_out;

    float *qkv_ptr, *vattn_ptr;
    cudaGetSymbolAddress((void**)&qkv_ptr, g_qkv);
    cudaGetSymbolAddress((void**)&vattn_ptr, g_vattn);

    // K1: qkv = BN(conv1x1(x))
    gemm_bn_kernel<<<dim3(16, 8, BATCH), 256>>>(
        x, qkv_w, qkv_g, qkv_b, qkv_m, qkv_v, qkv_ptr, QKV_OUT);

    // K2: attention -> g_vattn  (register-resident FA2, tf32 QK + bf16 PV)
    attn_kernel<<<dim3(8, NHEADS, BATCH), 256>>>(qkv_ptr, vattn_ptr);

    // K3: vattn += BN(dwconv3x3(v))
    pe_add_kernel<<<dim3(DIM, BATCH), 256>>>(
        qkv_ptr, pe_w, pe_g, pe_b, pe_m, pe_v, vattn_ptr);

    // K4: out = BN(conv1x1(vattn))
    gemm_bn_kernel<<<dim3(16, 4, BATCH), 256>>>(
        vattn_ptr, proj_w, proj_g, proj_b, proj_m, proj_v, out, DIM);
}

// round 6
// speedup vs baseline: 2.7497x; 1.4576x over previous
#include <cuda_runtime.h>
#include <cuda_bf16.h>
#include <math.h>
#include <stdint.h>

// Problem constants
#define BATCH 16
#define DIM 256
#define NHEADS 8
#define HEAD_DIM 32
#define KEY_DIM 16
#define NTOK 1024            // 32*32
#define QKV_OUT 512
#define BN_EPS 1e-3f
#define SCALE_F 0.25f        // KEY_DIM^-0.5
#define LOG2E 1.4426950408889634f

// Device scratch (allocation-free rule: static __device__ arrays)
__device__ float g_qkv[BATCH * QKV_OUT * NTOK];    // 33.5 MB
__device__ float g_vattn[BATCH * DIM * NTOK];      // 16.8 MB

// ---------------------------------------------------------------------------
// helpers
// ---------------------------------------------------------------------------
__device__ __forceinline__ float tf32r(float x) {
    uint32_t u;
    asm("cvt.rna.tf32.f32 %0, %1;" : "=r"(u) : "f"(x));
    return __uint_as_float(u);
}
__device__ __forceinline__ uint32_t pk2(float lo, float hi) {
    uint32_t r;  // lower half <- second source
    asm("cvt.rn.bf16x2.f32 %0, %1, %2;" : "=r"(r) : "f"(hi), "f"(lo));
    return r;
}
__device__ __forceinline__ float fex2(float x) {
    float y;
    asm("ex2.approx.ftz.f32 %0, %1;" : "=f"(y) : "f"(x));
    return y;
}
__device__ __forceinline__ void mma_tf32(
    float& d0, float& d1, float& d2, float& d3,
    uint32_t a0, uint32_t a1, uint32_t a2, uint32_t a3,
    uint32_t b0, uint32_t b1)
{
    asm volatile(
        "mma.sync.aligned.m16n8k8.row.col.f32.tf32.tf32.f32 "
        "{%0,%1,%2,%3}, {%4,%5,%6,%7}, {%8,%9}, {%0,%1,%2,%3};"
        : "+f"(d0), "+f"(d1), "+f"(d2), "+f"(d3)
        : "r"(a0), "r"(a1), "r"(a2), "r"(a3), "r"(b0), "r"(b1));
}
__device__ __forceinline__ void mma_bf16(
    float& d0, float& d1, float& d2, float& d3,
    uint32_t a0, uint32_t a1, uint32_t a2, uint32_t a3,
    uint32_t b0, uint32_t b1)
{
    asm volatile(
        "mma.sync.aligned.m16n8k16.row.col.f32.bf16.bf16.f32 "
        "{%0,%1,%2,%3}, {%4,%5,%6,%7}, {%8,%9}, {%0,%1,%2,%3};"
        : "+f"(d0), "+f"(d1), "+f"(d2), "+f"(d3)
        : "r"(a0), "r"(a1), "r"(a2), "r"(a3), "r"(b0), "r"(b1));
}

// ---------------------------------------------------------------------------
// K1/K4: tf32 tensor-core GEMM + BN.
// out[b,o,n] = BN( sum_c W[o,c] X[b,c,n] ), K=256, N=1024.
// CTA tile 128x128, 8 warps (2x4), warp tile 64x32, k-chunk 16 double-buffered.
// ---------------------------------------------------------------------------
#define GASTR 20
#define GBSTR 136

__global__ __launch_bounds__(256) void gemm_bn_tc(
    const float* __restrict__ X, const float* __restrict__ W,
    const float* __restrict__ gam, const float* __restrict__ bet,
    const float* __restrict__ mu, const float* __restrict__ va,
    float* __restrict__ out, int M)
{
    __shared__ __align__(16) float Af[2][128 * GASTR];  // 2*2560 floats
    __shared__ __align__(16) float Bf[2][16 * GBSTR];   // 2*2176 floats

    int b  = blockIdx.z;
    int o0 = blockIdx.y * 128;
    int n0 = blockIdx.x * 128;

    int tid = threadIdx.x, warp = tid >> 5, lane = tid & 31;
    int qr = lane >> 2, qc = lane & 3;
    int wm = (warp >> 2) * 64, wn = (warp & 3) * 32;

    const float* Xb = X + (size_t)b * 256 * NTOK;

    float C[4][4][4];
    #pragma unroll
    for (int i = 0; i < 4; i++)
        #pragma unroll
        for (int j = 0; j < 4; j++)
            #pragma unroll
            for (int r = 0; r < 4; r++) C[i][j][r] = 0.f;

    int arow = tid >> 1, acg = (tid & 1) * 8;   // A: 2 threads/row, 8 cols each
    int bkr  = tid >> 4, bnc = (tid & 15) * 8;  // B: 16 threads/row, 8 cols each

    float Ast[8], Bst[8];
    // prefetch chunk 0
    #pragma unroll
    for (int j = 0; j < 2; j++) {
        float4 t = *(const float4*)&W[(o0 + arow) * 256 + acg + 4 * j];
        Ast[4*j+0] = tf32r(t.x); Ast[4*j+1] = tf32r(t.y);
        Ast[4*j+2] = tf32r(t.z); Ast[4*j+3] = tf32r(t.w);
    }
    #pragma unroll
    for (int j = 0; j < 2; j++) {
        float4 t = *(const float4*)&Xb[bkr * NTOK + n0 + bnc + 4 * j];
        Bst[4*j+0] = tf32r(t.x); Bst[4*j+1] = tf32r(t.y);
        Bst[4*j+2] = tf32r(t.z); Bst[4*j+3] = tf32r(t.w);
    }

    for (int kc = 0; kc < 16; kc++) {
        float* Ab = Af[kc & 1];
        float* Bb = Bf[kc & 1];
        #pragma unroll
        for (int j = 0; j < 2; j++)
            *(float4*)&Ab[arow * GASTR + acg + 4 * j] =
                make_float4(Ast[4*j], Ast[4*j+1], Ast[4*j+2], Ast[4*j+3]);
        #pragma unroll
        for (int j = 0; j < 2; j++)
            *(float4*)&Bb[bkr * GBSTR + bnc + 4 * j] =
                make_float4(Bst[4*j], Bst[4*j+1], Bst[4*j+2], Bst[4*j+3]);
        __syncthreads();

        if (kc < 15) {
            int k0 = (kc + 1) * 16;
            #pragma unroll
            for (int j = 0; j < 2; j++) {
                float4 t = *(const float4*)&W[(o0 + arow) * 256 + k0 + acg + 4 * j];
                Ast[4*j+0] = tf32r(t.x); Ast[4*j+1] = tf32r(t.y);
                Ast[4*j+2] = tf32r(t.z); Ast[4*j+3] = tf32r(t.w);
            }
            #pragma unroll
            for (int j = 0; j < 2; j++) {
                float4 t = *(const float4*)&Xb[(k0 + bkr) * NTOK + n0 + bnc + 4 * j];
                Bst[4*j+0] = tf32r(t.x); Bst[4*j+1] = tf32r(t.y);
                Bst[4*j+2] = tf32r(t.z); Bst[4*j+3] = tf32r(t.w);
            }
        }

        #pragma unroll
        for (int ks = 0; ks < 2; ks++) {
            int kk = ks * 8;
            uint32_t af[4][4];
            #pragma unroll
            for (int mt = 0; mt < 4; mt++) {
                int r = wm + mt * 16 + qr;
                af[mt][0] = __float_as_uint(Ab[r * GASTR + kk + qc]);
                af[mt][1] = __float_as_uint(Ab[(r + 8) * GASTR + kk + qc]);
                af[mt][2] = __float_as_uint(Ab[r * GASTR + kk + qc + 4]);
                af[mt][3] = __float_as_uint(Ab[(r + 8) * GASTR + kk + qc + 4]);
            }
            uint32_t bfr[4][2];
            #pragma unroll
            for (int nt = 0; nt < 4; nt++) {
                bfr[nt][0] = __float_as_uint(Bb[(kk + qc) * GBSTR + wn + nt * 8 + qr]);
                bfr[nt][1] = __float_as_uint(Bb[(kk + qc + 4) * GBSTR + wn + nt * 8 + qr]);
            }
            #pragma unroll
            for (int mt = 0; mt < 4; mt++)
                #pragma unroll
                for (int nt = 0; nt < 4; nt++)
                    mma_tf32(C[mt][nt][0], C[mt][nt][1], C[mt][nt][2], C[mt][nt][3],
                             af[mt][0], af[mt][1], af[mt][2], af[mt][3],
                             bfr[nt][0], bfr[nt][1]);
        }
    }

    // epilogue: BN + store
    #pragma unroll
    for (int mt = 0; mt < 4; mt++) {
        int r_lo = o0 + wm + mt * 16 + qr;
        int r_hi = r_lo + 8;
        float inv0 = gam[r_lo] * rsqrtf(va[r_lo] + BN_EPS);
        float sh0  = bet[r_lo] - mu[r_lo] * inv0;
        float inv1 = gam[r_hi] * rsqrtf(va[r_hi] + BN_EPS);
        float sh1  = bet[r_hi] - mu[r_hi] * inv1;
        #pragma unroll
        for (int nt = 0; nt < 4; nt++) {
            int col = n0 + wn + nt * 8 + 2 * qc;
            *(float2*)&out[((size_t)b * M + r_lo) * NTOK + col] =
                make_float2(C[mt][nt][0] * inv0 + sh0, C[mt][nt][1] * inv0 + sh0);
            *(float2*)&out[((size_t)b * M + r_hi) * NTOK + col] =
                make_float2(C[mt][nt][2] * inv1 + sh1, C[mt][nt][3] * inv1 + sh1);
        }
    }
}

// ---------------------------------------------------------------------------
// K2: register-resident flash attention + fused dwconv3x3 pos-enc epilogue.
// ---------------------------------------------------------------------------
#define QSTR 21          // q stage stride (floats)
#define KSTRW 136        // K row stride in floats
#define VSTRW 68         // V row stride in words (bf16x2)
#define KBUF  (16 * KSTRW)            // 2176 floats
#define VBUF  (32 * VSTRW)            // 2176 words
#define BUFSZ (KBUF + VBUF)           // 4352 floats per stage
#define S_TOTAL (128 * QSTR + 2 * BUFSZ)   // 2688 + 8704 = 11392 floats

__global__ __launch_bounds__(256) void attn_kernel(
    const float* __restrict__ qkv, float* __restrict__ vattn,
    const float* __restrict__ pe_w,
    const float* __restrict__ pe_g, const float* __restrict__ pe_b,
    const float* __restrict__ pe_m, const float* __restrict__ pe_v)
{
    __shared__ __align__(16) float s_all[S_TOTAL];   // 45568 B
    float* s_q   = s_all;               // [128][QSTR]
    float* s_buf = s_all + 128 * QSTR;  // 2 stages of K/V

    int tid  = threadIdx.x;
    int b    = blockIdx.z, h = blockIdx.y;
    int m0   = blockIdx.x * 128;

    int warp = tid >> 5, lane = tid & 31;
    int qr = lane >> 2;       // 0..7
    int qc = lane & 3;        // 0..3
    int mw = warp * 16;

    const float* base = qkv + ((size_t)b * QKV_OUT + h * 64) * NTOK;

    // ---- stage q (scaled by SCALE*log2e, tf32-rounded) ----
    const float qsc = SCALE_F * LOG2E;
    for (int i = tid; i < 16 * 128; i += 256) {
        int d = i >> 7, mm = i & 127;
        s_q[mm * QSTR + d] = tf32r(base[d * NTOK + m0 + mm] * qsc);
    }
    __syncthreads();

    // hoist q A-fragments
    uint32_t aq[2][4];
    #pragma unroll
    for (int kk = 0; kk < 2; kk++) {
        aq[kk][0] = __float_as_uint(s_q[(mw + qr)     * QSTR + kk * 8 + qc]);
        aq[kk][1] = __float_as_uint(s_q[(mw + qr + 8) * QSTR + kk * 8 + qc]);
        aq[kk][2] = __float_as_uint(s_q[(mw + qr)     * QSTR + kk * 8 + qc + 4]);
        aq[kk][3] = __float_as_uint(s_q[(mw + qr + 8) * QSTR + kk * 8 + qc + 4]);
    }

    float om0 = -1e30f, om1 = -1e30f;
    float rs0 = 0.f, rs1 = 0.f;
    float O[4][4];
    #pragma unroll
    for (int i = 0; i < 4; i++)
        #pragma unroll
        for (int j = 0; j < 4; j++) O[i][j] = 0.f;

    float    kst[8];
    uint32_t vstg[8];

    // prefetch tile 0
    {
        #pragma unroll
        for (int j = 0; j < 2; j++) {
            int lin = tid + j * 256;
            int d = lin >> 5, n4 = (lin & 31) * 4;
            float4 t = *(const float4*)&base[(16 + d) * NTOK + n4];
            kst[4*j+0] = tf32r(t.x); kst[4*j+1] = tf32r(t.y);
            kst[4*j+2] = tf32r(t.z); kst[4*j+3] = tf32r(t.w);
        }
        #pragma unroll
        for (int j = 0; j < 4; j++) {
            int lin = tid + j * 256;
            int d = lin >> 5, n4 = (lin & 31) * 4;
            float4 t = *(const float4*)&base[(32 + d) * NTOK + n4];
            vstg[2*j]   = pk2(t.x, t.y);
            vstg[2*j+1] = pk2(t.z, t.w);
        }
    }

    for (int t = 0; t < 8; t++) {
        float*    kf = s_buf + (t & 1) * BUFSZ;
        uint32_t* vw = (uint32_t*)(kf + KBUF);
        #pragma unroll
        for (int j = 0; j < 2; j++) {
            int lin = tid + j * 256;
            int d = lin >> 5, n4 = (lin & 31) * 4;
            *(float4*)&kf[d * KSTRW + n4] =
                make_float4(kst[4*j], kst[4*j+1], kst[4*j+2], kst[4*j+3]);
        }
        #pragma unroll
        for (int j = 0; j < 4; j++) {
            int lin = tid + j * 256;
            int d = lin >> 5, n4 = (lin & 31) * 4;
            *(uint2*)&vw[d * VSTRW + (n4 >> 1)] = make_uint2(vstg[2*j], vstg[2*j+1]);
        }
        __syncthreads();

        if (t < 7) {
            int n0 = (t + 1) * 128;
            #pragma unroll
            for (int j = 0; j < 2; j++) {
                int lin = tid + j * 256;
                int d = lin >> 5, n4 = (lin & 31) * 4;
                float4 tt = *(const float4*)&base[(16 + d) * NTOK + n0 + n4];
                kst[4*j+0] = tf32r(tt.x); kst[4*j+1] = tf32r(tt.y);
                kst[4*j+2] = tf32r(tt.z); kst[4*j+3] = tf32r(tt.w);
            }
            #pragma unroll
            for (int j = 0; j < 4; j++) {
                int lin = tid + j * 256;
                int d = lin >> 5, n4 = (lin & 31) * 4;
                float4 tt = *(const float4*)&base[(32 + d) * NTOK + n0 + n4];
                vstg[2*j]   = pk2(tt.x, tt.y);
                vstg[2*j+1] = pk2(tt.z, tt.w);
            }
        }

        // ---- QK
        float S[16][4];
        #pragma unroll
        for (int nt = 0; nt < 16; nt++) {
            float d0 = 0.f, d1 = 0.f, d2 = 0.f, d3 = 0.f;
            #pragma unroll
            for (int kk = 0; kk < 2; kk++) {
                uint32_t b0 = __float_as_uint(kf[(kk*8 + qc)     * KSTRW + nt*8 + qr]);
                uint32_t b1 = __float_as_uint(kf[(kk*8 + qc + 4) * KSTRW + nt*8 + qr]);
                mma_tf32(d0, d1, d2, d3,
                         aq[kk][0], aq[kk][1], aq[kk][2], aq[kk][3], b0, b1);
            }
            S[nt][0] = d0; S[nt][1] = d1; S[nt][2] = d2; S[nt][3] = d3;
        }

        // ---- register softmax (base-2)
        float tm0 = -1e30f, tm1 = -1e30f;
        #pragma unroll
        for (int nt = 0; nt < 16; nt++) {
            tm0 = fmaxf(tm0, fmaxf(S[nt][0], S[nt][1]));
            tm1 = fmaxf(tm1, fmaxf(S[nt][2], S[nt][3]));
        }
        tm0 = fmaxf(tm0, __shfl_xor_sync(0xffffffffu, tm0, 1));
        tm0 = fmaxf(tm0, __shfl_xor_sync(0xffffffffu, tm0, 2));
        tm1 = fmaxf(tm1, __shfl_xor_sync(0xffffffffu, tm1, 1));
        tm1 = fmaxf(tm1, __shfl_xor_sync(0xffffffffu, tm1, 2));

        float nm0 = fmaxf(om0, tm0), nm1 = fmaxf(om1, tm1);
        float f0 = fex2(om0 - nm0),  f1 = fex2(om1 - nm1);
        om0 = nm0; om1 = nm1;

        float ps0 = 0.f, ps1 = 0.f;
        #pragma unroll
        for (int nt = 0; nt < 16; nt++) {
            float e0 = fex2(S[nt][0] - nm0);
            float e1 = fex2(S[nt][1] - nm0);
            float e2 = fex2(S[nt][2] - nm1);
            float e3 = fex2(S[nt][3] - nm1);
            S[nt][0] = e0; S[nt][1] = e1; S[nt][2] = e2; S[nt][3] = e3;
            ps0 += e0 + e1; ps1 += e2 + e3;
        }
        rs0 = rs0 * f0 + ps0;
        rs1 = rs1 * f1 + ps1;
        #pragma unroll
        for (int dt = 0; dt < 4; dt++) {
            O[dt][0] *= f0; O[dt][1] *= f0;
            O[dt][2] *= f1; O[dt][3] *= f1;
        }

        // ---- PV (bf16)
        #pragma unroll
        for (int kt = 0; kt < 8; kt++) {
            uint32_t a0 = pk2(S[2*kt][0],   S[2*kt][1]);
            uint32_t a1 = pk2(S[2*kt][2],   S[2*kt][3]);
            uint32_t a2 = pk2(S[2*kt+1][0], S[2*kt+1][1]);
            uint32_t a3 = pk2(S[2*kt+1][2], S[2*kt+1][3]);
            #pragma unroll
            for (int dt = 0; dt < 4; dt++) {
                uint32_t b0 = vw[(dt*8 + qr) * VSTRW + kt*8 + qc];
                uint32_t b1 = vw[(dt*8 + qr) * VSTRW + kt*8 + qc + 4];
                mma_bf16(O[dt][0], O[dt][1], O[dt][2], O[dt][3],
                         a0, a1, a2, a3, b0, b1);
            }
        }
    }
    __syncthreads();   // all PV reads done; smem arena is now free for reuse

    // final row sums
    rs0 += __shfl_xor_sync(0xffffffffu, rs0, 1);
    rs0 += __shfl_xor_sync(0xffffffffu, rs0, 2);
    rs1 += __shfl_xor_sync(0xffffffffu, rs1, 1);
    rs1 += __shfl_xor_sync(0xffffffffu, rs1, 2);
    float inv0 = 1.0f / rs0, inv1 = 1.0f / rs1;

    // epilogue smem overlay
    float* ob   = s_all;            // [128][33]  = 4224
    float* pv   = s_all + 4224;     // [32][6][34] = 6528
    float* pwb  = s_all + 10752;    // 32*9 = 288
    float* pinv = s_all + 11040;    // 32
    float* psh  = s_all + 11072;    // 32

    // write O frags (scalar stores; odd stride 33 keeps transposed read clean)
    #pragma unroll
    for (int dt = 0; dt < 4; dt++) {
        ob[(mw + qr)     * 33 + dt*8 + 2*qc]     = O[dt][0] * inv0;
        ob[(mw + qr)     * 33 + dt*8 + 2*qc + 1] = O[dt][1] * inv0;
        ob[(mw + qr + 8) * 33 + dt*8 + 2*qc]     = O[dt][2] * inv1;
        ob[(mw + qr + 8) * 33 + dt*8 + 2*qc + 1] = O[dt][3] * inv1;
    }

    // load v halo [32ch][6 rows][34 cols] with zero padding, + pe params
    {
        int r0 = blockIdx.x * 4;                 // image row base of this tile
        const float* vbase = base + 32 * NTOK;
        for (int i = tid; i < 32 * 6 * 34; i += 256) {
            int d  = i / 204;
            int rm = i % 204;
            int yy = rm / 34;
            int xx = rm % 34;
            int x  = xx - 1;
            int ry = r0 - 1 + yy;
            float val = 0.f;
            if ((unsigned)x < 32u && (unsigned)ry < 32u)
                val = vbase[d * NTOK + ry * 32 + x];
            pv[i] = val;
        }
        for (int i = tid; i < 288; i += 256)       // FIX: full 288 weights
            pwb[i] = pe_w[h * 32 * 9 + i];
        if (tid < 32) {
            int c = h * 32 + tid;
            float iv = pe_g[c] * rsqrtf(pe_v[c] + BN_EPS);
            pinv[tid] = iv;
            psh[tid]  = pe_b[c] - pe_m[c] * iv;
        }
    }
    __syncthreads();

    // out = v_attn + BN(dwconv3x3(v))
    float* outp = vattn + ((size_t)b * DIM + h * HEAD_DIM) * NTOK + m0;
    for (int i = tid; i < 32 * 128; i += 256) {
        int d = i >> 7, mm = i & 127;
        int y = mm >> 5, x = mm & 31;
        const float* wd = &pwb[d * 9];
        const float* p0 = &pv[d * 204 + y * 34 + x];
        float pe = wd[0]*p0[0]  + wd[1]*p0[1]  + wd[2]*p0[2]
                 + wd[3]*p0[34] + wd[4]*p0[35] + wd[5]*p0[36]
                 + wd[6]*p0[68] + wd[7]*p0[69] + wd[8]*p0[70];
        outp[d * NTOK + mm] = ob[mm * 33 + d] + pe * pinv[d] + psh[d];
    }
}

// ---------------------------------------------------------------------------
extern "C" void kernel_launch(void* const* d_in, const int* in_sizes, int n_in,
                              void* d_out, int out_size)
{
    const float* x        = (const float*)d_in[0];
    const float* qkv_w    = (const float*)d_in[1];
    const float* qkv_g    = (const float*)d_in[2];
    const float* qkv_b    = (const float*)d_in[3];
    const float* qkv_m    = (const float*)d_in[4];
    const float* qkv_v    = (const float*)d_in[5];
    const float* pe_w     = (const float*)d_in[6];
    const float* pe_g     = (const float*)d_in[7];
    const float* pe_b     = (const float*)d_in[8];
    const float* pe_m     = (const float*)d_in[9];
    const float* pe_v     = (const float*)d_in[10];
    const float* proj_w   = (const float*)d_in[11];
    const float* proj_g   = (const float*)d_in[12];
    const float* proj_b   = (const float*)d_in[13];
    const float* proj_m   = (const float*)d_in[14];
    const float* proj_v   = (const float*)d_in[15];
    float* out            = (float*)d_out;

    float *qkv_ptr, *vattn_ptr;
    cudaGetSymbolAddress((void**)&qkv_ptr, g_qkv);
    cudaGetSymbolAddress((void**)&vattn_ptr, g_vattn);

    // K1: qkv = BN(conv1x1(x))  — tf32 tensor cores
    gemm_bn_tc<<<dim3(8, 4, BATCH), 256>>>(
        x, qkv_w, qkv_g, qkv_b, qkv_m, qkv_v, qkv_ptr, QKV_OUT);

    // K2: attention + fused pos-enc -> g_vattn
    attn_kernel<<<dim3(8, NHEADS, BATCH), 256>>>(
        qkv_ptr, vattn_ptr, pe_w, pe_g, pe_b, pe_m, pe_v);

    // K4: out = BN(conv1x1(vattn))  — tf32 tensor cores
    gemm_bn_tc<<<dim3(8, 2, BATCH), 256>>>(
        vattn_ptr, proj_w, proj_g, proj_b, proj_m, proj_v, out, DIM);
}

// round 7
// speedup vs baseline: 3.2491x; 1.1816x over previous
#include <cuda_runtime.h>
#include <cuda_bf16.h>
#include <math.h>
#include <stdint.h>

// Problem constants
#define BATCH 16
#define DIM 256
#define NHEADS 8
#define HEAD_DIM 32
#define KEY_DIM 16
#define NTOK 1024            // 32*32
#define QKV_OUT 512
#define BN_EPS 1e-3f
#define SCALE_F 0.25f        // KEY_DIM^-0.5
#define LOG2E 1.4426950408889634f

// Device scratch (allocation-free rule: static __device__ arrays)
__device__ float g_qkv[BATCH * QKV_OUT * NTOK];    // 33.5 MB
__device__ float g_vattn[BATCH * DIM * NTOK];      // 16.8 MB

// ---------------------------------------------------------------------------
// helpers
// ---------------------------------------------------------------------------
__device__ __forceinline__ float tf32r(float x) {
    uint32_t u;
    asm("cvt.rna.tf32.f32 %0, %1;" : "=r"(u) : "f"(x));
    return __uint_as_float(u);
}
__device__ __forceinline__ uint32_t pk2(float lo, float hi) {
    uint32_t r;  // lower half <- second source
    asm("cvt.rn.bf16x2.f32 %0, %1, %2;" : "=r"(r) : "f"(hi), "f"(lo));
    return r;
}
__device__ __forceinline__ float fex2(float x) {
    float y;
    asm("ex2.approx.ftz.f32 %0, %1;" : "=f"(y) : "f"(x));
    return y;
}
__device__ __forceinline__ void mma_tf32(
    float& d0, float& d1, float& d2, float& d3,
    uint32_t a0, uint32_t a1, uint32_t a2, uint32_t a3,
    uint32_t b0, uint32_t b1)
{
    asm volatile(
        "mma.sync.aligned.m16n8k8.row.col.f32.tf32.tf32.f32 "
        "{%0,%1,%2,%3}, {%4,%5,%6,%7}, {%8,%9}, {%0,%1,%2,%3};"
        : "+f"(d0), "+f"(d1), "+f"(d2), "+f"(d3)
        : "r"(a0), "r"(a1), "r"(a2), "r"(a3), "r"(b0), "r"(b1));
}
__device__ __forceinline__ void mma_bf16(
    float& d0, float& d1, float& d2, float& d3,
    uint32_t a0, uint32_t a1, uint32_t a2, uint32_t a3,
    uint32_t b0, uint32_t b1)
{
    asm volatile(
        "mma.sync.aligned.m16n8k16.row.col.f32.bf16.bf16.f32 "
        "{%0,%1,%2,%3}, {%4,%5,%6,%7}, {%8,%9}, {%0,%1,%2,%3};"
        : "+f"(d0), "+f"(d1), "+f"(d2), "+f"(d3)
        : "r"(a0), "r"(a1), "r"(a2), "r"(a3), "r"(b0), "r"(b1));
}

// ---------------------------------------------------------------------------
// K1/K4: tf32 tensor-core GEMM + BN (unchanged from round 6).
// ---------------------------------------------------------------------------
#define GASTR 20
#define GBSTR 136

__global__ __launch_bounds__(256) void gemm_bn_tc(
    const float* __restrict__ X, const float* __restrict__ W,
    const float* __restrict__ gam, const float* __restrict__ bet,
    const float* __restrict__ mu, const float* __restrict__ va,
    float* __restrict__ out, int M)
{
    __shared__ __align__(16) float Af[2][128 * GASTR];
    __shared__ __align__(16) float Bf[2][16 * GBSTR];

    int b  = blockIdx.z;
    int o0 = blockIdx.y * 128;
    int n0 = blockIdx.x * 128;

    int tid = threadIdx.x, warp = tid >> 5, lane = tid & 31;
    int qr = lane >> 2, qc = lane & 3;
    int wm = (warp >> 2) * 64, wn = (warp & 3) * 32;

    const float* Xb = X + (size_t)b * 256 * NTOK;

    float C[4][4][4];
    #pragma unroll
    for (int i = 0; i < 4; i++)
        #pragma unroll
        for (int j = 0; j < 4; j++)
            #pragma unroll
            for (int r = 0; r < 4; r++) C[i][j][r] = 0.f;

    int arow = tid >> 1, acg = (tid & 1) * 8;
    int bkr  = tid >> 4, bnc = (tid & 15) * 8;

    float Ast[8], Bst[8];
    #pragma unroll
    for (int j = 0; j < 2; j++) {
        float4 t = *(const float4*)&W[(o0 + arow) * 256 + acg + 4 * j];
        Ast[4*j+0] = tf32r(t.x); Ast[4*j+1] = tf32r(t.y);
        Ast[4*j+2] = tf32r(t.z); Ast[4*j+3] = tf32r(t.w);
    }
    #pragma unroll
    for (int j = 0; j < 2; j++) {
        float4 t = *(const float4*)&Xb[bkr * NTOK + n0 + bnc + 4 * j];
        Bst[4*j+0] = tf32r(t.x); Bst[4*j+1] = tf32r(t.y);
        Bst[4*j+2] = tf32r(t.z); Bst[4*j+3] = tf32r(t.w);
    }

    for (int kc = 0; kc < 16; kc++) {
        float* Ab = Af[kc & 1];
        float* Bb = Bf[kc & 1];
        #pragma unroll
        for (int j = 0; j < 2; j++)
            *(float4*)&Ab[arow * GASTR + acg + 4 * j] =
                make_float4(Ast[4*j], Ast[4*j+1], Ast[4*j+2], Ast[4*j+3]);
        #pragma unroll
        for (int j = 0; j < 2; j++)
            *(float4*)&Bb[bkr * GBSTR + bnc + 4 * j] =
                make_float4(Bst[4*j], Bst[4*j+1], Bst[4*j+2], Bst[4*j+3]);
        __syncthreads();

        if (kc < 15) {
            int k0 = (kc + 1) * 16;
            #pragma unroll
            for (int j = 0; j < 2; j++) {
                float4 t = *(const float4*)&W[(o0 + arow) * 256 + k0 + acg + 4 * j];
                Ast[4*j+0] = tf32r(t.x); Ast[4*j+1] = tf32r(t.y);
                Ast[4*j+2] = tf32r(t.z); Ast[4*j+3] = tf32r(t.w);
            }
            #pragma unroll
            for (int j = 0; j < 2; j++) {
                float4 t = *(const float4*)&Xb[(k0 + bkr) * NTOK + n0 + bnc + 4 * j];
                Bst[4*j+0] = tf32r(t.x); Bst[4*j+1] = tf32r(t.y);
                Bst[4*j+2] = tf32r(t.z); Bst[4*j+3] = tf32r(t.w);
            }
        }

        #pragma unroll
        for (int ks = 0; ks < 2; ks++) {
            int kk = ks * 8;
            uint32_t af[4][4];
            #pragma unroll
            for (int mt = 0; mt < 4; mt++) {
                int r = wm + mt * 16 + qr;
                af[mt][0] = __float_as_uint(Ab[r * GASTR + kk + qc]);
                af[mt][1] = __float_as_uint(Ab[(r + 8) * GASTR + kk + qc]);
                af[mt][2] = __float_as_uint(Ab[r * GASTR + kk + qc + 4]);
                af[mt][3] = __float_as_uint(Ab[(r + 8) * GASTR + kk + qc + 4]);
            }
            uint32_t bfr[4][2];
            #pragma unroll
            for (int nt = 0; nt < 4; nt++) {
                bfr[nt][0] = __float_as_uint(Bb[(kk + qc) * GBSTR + wn + nt * 8 + qr]);
                bfr[nt][1] = __float_as_uint(Bb[(kk + qc + 4) * GBSTR + wn + nt * 8 + qr]);
            }
            #pragma unroll
            for (int mt = 0; mt < 4; mt++)
                #pragma unroll
                for (int nt = 0; nt < 4; nt++)
                    mma_tf32(C[mt][nt][0], C[mt][nt][1], C[mt][nt][2], C[mt][nt][3],
                             af[mt][0], af[mt][1], af[mt][2], af[mt][3],
                             bfr[nt][0], bfr[nt][1]);
        }
    }

    #pragma unroll
    for (int mt = 0; mt < 4; mt++) {
        int r_lo = o0 + wm + mt * 16 + qr;
        int r_hi = r_lo + 8;
        float inv0 = gam[r_lo] * rsqrtf(va[r_lo] + BN_EPS);
        float sh0  = bet[r_lo] - mu[r_lo] * inv0;
        float inv1 = gam[r_hi] * rsqrtf(va[r_hi] + BN_EPS);
        float sh1  = bet[r_hi] - mu[r_hi] * inv1;
        #pragma unroll
        for (int nt = 0; nt < 4; nt++) {
            int col = n0 + wn + nt * 8 + 2 * qc;
            *(float2*)&out[((size_t)b * M + r_lo) * NTOK + col] =
                make_float2(C[mt][nt][0] * inv0 + sh0, C[mt][nt][1] * inv0 + sh0);
            *(float2*)&out[((size_t)b * M + r_hi) * NTOK + col] =
                make_float2(C[mt][nt][2] * inv1 + sh1, C[mt][nt][3] * inv1 + sh1);
        }
    }
}

// ---------------------------------------------------------------------------
// K2: register-resident flash attention, 64-key tiles (16 tiles) to cut
// register pressure (S: 32 regs) -> 2 CTAs/SM. Fused pos-enc epilogue.
// ---------------------------------------------------------------------------
#define QSTR 21          // q stage stride (floats)
#define KSTR2 72         // K row stride (floats): banks 8qc+qr distinct
#define VSTR2 36         // V row stride (words):  banks 4qr+qc distinct
#define KBUF2 (16 * KSTR2)            // 1152 floats
#define VBUF2 (32 * VSTR2)            // 1152 words
#define BUFSZ2 (KBUF2 + VBUF2)        // 2304 floats per stage
// epilogue overlay needs 11104 floats; main loop needs 2688+4608=7296
#define S_TOTAL2 11104

__global__ __launch_bounds__(256, 2) void attn_kernel(
    const float* __restrict__ qkv, float* __restrict__ vattn,
    const float* __restrict__ pe_w,
    const float* __restrict__ pe_g, const float* __restrict__ pe_b,
    const float* __restrict__ pe_m, const float* __restrict__ pe_v)
{
    __shared__ __align__(16) float s_all[S_TOTAL2];   // 44416 B
    float* s_q   = s_all;               // [128][QSTR]
    float* s_buf = s_all + 128 * QSTR;  // 2 stages of K/V (64-key tiles)

    int tid  = threadIdx.x;
    int b    = blockIdx.z, h = blockIdx.y;
    int m0   = blockIdx.x * 128;

    int warp = tid >> 5, lane = tid & 31;
    int qr = lane >> 2;       // 0..7
    int qc = lane & 3;        // 0..3
    int mw = warp * 16;

    const float* base = qkv + ((size_t)b * QKV_OUT + h * 64) * NTOK;

    // ---- stage q (scaled by SCALE*log2e, tf32-rounded) ----
    const float qsc = SCALE_F * LOG2E;
    for (int i = tid; i < 16 * 128; i += 256) {
        int d = i >> 7, mm = i & 127;
        s_q[mm * QSTR + d] = tf32r(base[d * NTOK + m0 + mm] * qsc);
    }
    __syncthreads();

    uint32_t aq[2][4];
    #pragma unroll
    for (int kk = 0; kk < 2; kk++) {
        aq[kk][0] = __float_as_uint(s_q[(mw + qr)     * QSTR + kk * 8 + qc]);
        aq[kk][1] = __float_as_uint(s_q[(mw + qr + 8) * QSTR + kk * 8 + qc]);
        aq[kk][2] = __float_as_uint(s_q[(mw + qr)     * QSTR + kk * 8 + qc + 4]);
        aq[kk][3] = __float_as_uint(s_q[(mw + qr + 8) * QSTR + kk * 8 + qc + 4]);
    }

    float om0 = -1e30f, om1 = -1e30f;
    float rs0 = 0.f, rs1 = 0.f;
    float O[4][4];
    #pragma unroll
    for (int i = 0; i < 4; i++)
        #pragma unroll
        for (int j = 0; j < 4; j++) O[i][j] = 0.f;

    // per-tile staging: K 1 float4/thread, V 2 float4 -> 4 words
    float    kst[4];
    uint32_t vstg[4];

    int kd = tid >> 4;              // 0..15 (K row)
    int kn4 = (tid & 15) * 4;       // K col group

    // prefetch tile 0
    {
        float4 t = *(const float4*)&base[(16 + kd) * NTOK + kn4];
        kst[0] = tf32r(t.x); kst[1] = tf32r(t.y);
        kst[2] = tf32r(t.z); kst[3] = tf32r(t.w);
        #pragma unroll
        for (int j = 0; j < 2; j++) {
            int lin = tid + j * 256;
            int d = lin >> 4, n4 = (lin & 15) * 4;
            float4 v = *(const float4*)&base[(32 + d) * NTOK + n4];
            vstg[2*j]   = pk2(v.x, v.y);
            vstg[2*j+1] = pk2(v.z, v.w);
        }
    }

    for (int t = 0; t < 16; t++) {
        float*    kf = s_buf + (t & 1) * BUFSZ2;
        uint32_t* vw = (uint32_t*)(kf + KBUF2);
        *(float4*)&kf[kd * KSTR2 + kn4] =
            make_float4(kst[0], kst[1], kst[2], kst[3]);
        #pragma unroll
        for (int j = 0; j < 2; j++) {
            int lin = tid + j * 256;
            int d = lin >> 4, n4 = (lin & 15) * 4;
            *(uint2*)&vw[d * VSTR2 + (n4 >> 1)] = make_uint2(vstg[2*j], vstg[2*j+1]);
        }
        __syncthreads();

        if (t < 15) {
            int n0 = (t + 1) * 64;
            float4 tt = *(const float4*)&base[(16 + kd) * NTOK + n0 + kn4];
            kst[0] = tf32r(tt.x); kst[1] = tf32r(tt.y);
            kst[2] = tf32r(tt.z); kst[3] = tf32r(tt.w);
            #pragma unroll
            for (int j = 0; j < 2; j++) {
                int lin = tid + j * 256;
                int d = lin >> 4, n4 = (lin & 15) * 4;
                float4 v = *(const float4*)&base[(32 + d) * NTOK + n0 + n4];
                vstg[2*j]   = pk2(v.x, v.y);
                vstg[2*j+1] = pk2(v.z, v.w);
            }
        }

        // ---- QK: S 16x64 in regs (8 n-tiles)
        float S[8][4];
        #pragma unroll
        for (int nt = 0; nt < 8; nt++) {
            float d0 = 0.f, d1 = 0.f, d2 = 0.f, d3 = 0.f;
            #pragma unroll
            for (int kk = 0; kk < 2; kk++) {
                uint32_t b0 = __float_as_uint(kf[(kk*8 + qc)     * KSTR2 + nt*8 + qr]);
                uint32_t b1 = __float_as_uint(kf[(kk*8 + qc + 4) * KSTR2 + nt*8 + qr]);
                mma_tf32(d0, d1, d2, d3,
                         aq[kk][0], aq[kk][1], aq[kk][2], aq[kk][3], b0, b1);
            }
            S[nt][0] = d0; S[nt][1] = d1; S[nt][2] = d2; S[nt][3] = d3;
        }

        // ---- register softmax (base-2)
        float tm0 = -1e30f, tm1 = -1e30f;
        #pragma unroll
        for (int nt = 0; nt < 8; nt++) {
            tm0 = fmaxf(tm0, fmaxf(S[nt][0], S[nt][1]));
            tm1 = fmaxf(tm1, fmaxf(S[nt][2], S[nt][3]));
        }
        tm0 = fmaxf(tm0, __shfl_xor_sync(0xffffffffu, tm0, 1));
        tm0 = fmaxf(tm0, __shfl_xor_sync(0xffffffffu, tm0, 2));
        tm1 = fmaxf(tm1, __shfl_xor_sync(0xffffffffu, tm1, 1));
        tm1 = fmaxf(tm1, __shfl_xor_sync(0xffffffffu, tm1, 2));

        float nm0 = fmaxf(om0, tm0), nm1 = fmaxf(om1, tm1);
        float f0 = fex2(om0 - nm0),  f1 = fex2(om1 - nm1);
        om0 = nm0; om1 = nm1;

        float ps0 = 0.f, ps1 = 0.f;
        #pragma unroll
        for (int nt = 0; nt < 8; nt++) {
            float e0 = fex2(S[nt][0] - nm0);
            float e1 = fex2(S[nt][1] - nm0);
            float e2 = fex2(S[nt][2] - nm1);
            float e3 = fex2(S[nt][3] - nm1);
            S[nt][0] = e0; S[nt][1] = e1; S[nt][2] = e2; S[nt][3] = e3;
            ps0 += e0 + e1; ps1 += e2 + e3;
        }
        rs0 = rs0 * f0 + ps0;
        rs1 = rs1 * f1 + ps1;
        #pragma unroll
        for (int dt = 0; dt < 4; dt++) {
            O[dt][0] *= f0; O[dt][1] *= f0;
            O[dt][2] *= f1; O[dt][3] *= f1;
        }

        // ---- PV (bf16): 4 k-steps of 16 keys
        #pragma unroll
        for (int kt = 0; kt < 4; kt++) {
            uint32_t a0 = pk2(S[2*kt][0],   S[2*kt][1]);
            uint32_t a1 = pk2(S[2*kt][2],   S[2*kt][3]);
            uint32_t a2 = pk2(S[2*kt+1][0], S[2*kt+1][1]);
            uint32_t a3 = pk2(S[2*kt+1][2], S[2*kt+1][3]);
            #pragma unroll
            for (int dt = 0; dt < 4; dt++) {
                uint32_t b0 = vw[(dt*8 + qr) * VSTR2 + kt*8 + qc];
                uint32_t b1 = vw[(dt*8 + qr) * VSTR2 + kt*8 + qc + 4];
                mma_bf16(O[dt][0], O[dt][1], O[dt][2], O[dt][3],
                         a0, a1, a2, a3, b0, b1);
            }
        }
    }
    __syncthreads();   // all PV reads done; smem arena free for reuse

    // final row sums
    rs0 += __shfl_xor_sync(0xffffffffu, rs0, 1);
    rs0 += __shfl_xor_sync(0xffffffffu, rs0, 2);
    rs1 += __shfl_xor_sync(0xffffffffu, rs1, 1);
    rs1 += __shfl_xor_sync(0xffffffffu, rs1, 2);
    float inv0 = 1.0f / rs0, inv1 = 1.0f / rs1;

    // epilogue smem overlay
    float* ob   = s_all;            // [128][33]  = 4224
    float* pv   = s_all + 4224;     // [32][6][34] = 6528
    float* pwb  = s_all + 10752;    // 288
    float* pinv = s_all + 11040;    // 32
    float* psh  = s_all + 11072;    // 32

    #pragma unroll
    for (int dt = 0; dt < 4; dt++) {
        ob[(mw + qr)     * 33 + dt*8 + 2*qc]     = O[dt][0] * inv0;
        ob[(mw + qr)     * 33 + dt*8 + 2*qc + 1] = O[dt][1] * inv0;
        ob[(mw + qr + 8) * 33 + dt*8 + 2*qc]     = O[dt][2] * inv1;
        ob[(mw + qr + 8) * 33 + dt*8 + 2*qc + 1] = O[dt][3] * inv1;
    }

    // load v halo [32ch][6 rows][34 cols] with zero padding, + pe params
    {
        int r0 = blockIdx.x * 4;
        const float* vbase = base + 32 * NTOK;
        for (int i = tid; i < 32 * 6 * 34; i += 256) {
            int d  = i / 204;
            int rm = i % 204;
            int yy = rm / 34;
            int xx = rm % 34;
            int x  = xx - 1;
            int ry = r0 - 1 + yy;
            float val = 0.f;
            if ((unsigned)x < 32u && (unsigned)ry < 32u)
                val = vbase[d * NTOK + ry * 32 + x];
            pv[i] = val;
        }
        for (int i = tid; i < 288; i += 256)
            pwb[i] = pe_w[h * 32 * 9 + i];
        if (tid < 32) {
            int c = h * 32 + tid;
            float iv = pe_g[c] * rsqrtf(pe_v[c] + BN_EPS);
            pinv[tid] = iv;
            psh[tid]  = pe_b[c] - pe_m[c] * iv;
        }
    }
    __syncthreads();

    // out = v_attn + BN(dwconv3x3(v))
    float* outp = vattn + ((size_t)b * DIM + h * HEAD_DIM) * NTOK + m0;
    for (int i = tid; i < 32 * 128; i += 256) {
        int d = i >> 7, mm = i & 127;
        int y = mm >> 5, x = mm & 31;
        const float* wd = &pwb[d * 9];
        const float* p0 = &pv[d * 204 + y * 34 + x];
        float pe = wd[0]*p0[0]  + wd[1]*p0[1]  + wd[2]*p0[2]
                 + wd[3]*p0[34] + wd[4]*p0[35] + wd[5]*p0[36]
                 + wd[6]*p0[68] + wd[7]*p0[69] + wd[8]*p0[70];
        outp[d * NTOK + mm] = ob[mm * 33 + d] + pe * pinv[d] + psh[d];
    }
}

// ---------------------------------------------------------------------------
extern "C" void kernel_launch(void* const* d_in, const int* in_sizes, int n_in,
                              void* d_out, int out_size)
{
    const float* x        = (const float*)d_in[0];
    const float* qkv_w    = (const float*)d_in[1];
    const float* qkv_g    = (const float*)d_in[2];
    const float* qkv_b    = (const float*)d_in[3];
    const float* qkv_m    = (const float*)d_in[4];
    const float* qkv_v    = (const float*)d_in[5];
    const float* pe_w     = (const float*)d_in[6];
    const float* pe_g     = (const float*)d_in[7];
    const float* pe_b     = (const float*)d_in[8];
    const float* pe_m     = (const float*)d_in[9];
    const float* pe_v     = (const float*)d_in[10];
    const float* proj_w   = (const float*)d_in[11];
    const float* proj_g   = (const float*)d_in[12];
    const float* proj_b   = (const float*)d_in[13];
    const float* proj_m   = (const float*)d_in[14];
    const float* proj_v   = (const float*)d_in[15];
    float* out            = (float*)d_out;

    float *qkv_ptr, *vattn_ptr;
    cudaGetSymbolAddress((void**)&qkv_ptr, g_qkv);
    cudaGetSymbolAddress((void**)&vattn_ptr, g_vattn);

    // K1: qkv = BN(conv1x1(x))  — tf32 tensor cores
    gemm_bn_tc<<<dim3(8, 4, BATCH), 256>>>(
        x, qkv_w, qkv_g, qkv_b, qkv_m, qkv_v, qkv_ptr, QKV_OUT);

    // K2: attention + fused pos-enc -> g_vattn
    attn_kernel<<<dim3(8, NHEADS, BATCH), 256>>>(
        qkv_ptr, vattn_ptr, pe_w, pe_g, pe_b, pe_m, pe_v);

    // K4: out = BN(conv1x1(vattn))  — tf32 tensor cores
    gemm_bn_tc<<<dim3(8, 2, BATCH), 256>>>(
        vattn_ptr, proj_w, proj_g, proj_b, proj_m, proj_v, out, DIM);
}

// round 8
// speedup vs baseline: 3.3389x; 1.0276x over previous
#include <cuda_runtime.h>
#include <cuda_bf16.h>
#include <math.h>
#include <stdint.h>

// Problem constants
#define BATCH 16
#define DIM 256
#define NHEADS 8
#define HEAD_DIM 32
#define KEY_DIM 16
#define NTOK 1024            // 32*32
#define QKV_OUT 512
#define BN_EPS 1e-3f
#define SCALE_F 0.25f        // KEY_DIM^-0.5
#define LOG2E 1.4426950408889634f

// Device scratch (allocation-free rule: static __device__ arrays)
__device__ float g_qkv[BATCH * QKV_OUT * NTOK];    // 33.5 MB
__device__ float g_vattn[BATCH * DIM * NTOK];      // 16.8 MB

// ---------------------------------------------------------------------------
// helpers
// ---------------------------------------------------------------------------
__device__ __forceinline__ float tf32r(float x) {
    uint32_t u;
    asm("cvt.rna.tf32.f32 %0, %1;" : "=r"(u) : "f"(x));
    return __uint_as_float(u);
}
__device__ __forceinline__ uint32_t tf32u(float x) {
    uint32_t u;
    asm("cvt.rna.tf32.f32 %0, %1;" : "=r"(u) : "f"(x));
    return u;
}
__device__ __forceinline__ uint32_t pk2(float lo, float hi) {
    uint32_t r;  // lower half <- second source
    asm("cvt.rn.bf16x2.f32 %0, %1, %2;" : "=r"(r) : "f"(hi), "f"(lo));
    return r;
}
__device__ __forceinline__ float fex2(float x) {
    float y;
    asm("ex2.approx.ftz.f32 %0, %1;" : "=f"(y) : "f"(x));
    return y;
}
__device__ __forceinline__ void mma_tf32(
    float& d0, float& d1, float& d2, float& d3,
    uint32_t a0, uint32_t a1, uint32_t a2, uint32_t a3,
    uint32_t b0, uint32_t b1)
{
    asm volatile(
        "mma.sync.aligned.m16n8k8.row.col.f32.tf32.tf32.f32 "
        "{%0,%1,%2,%3}, {%4,%5,%6,%7}, {%8,%9}, {%0,%1,%2,%3};"
        : "+f"(d0), "+f"(d1), "+f"(d2), "+f"(d3)
        : "r"(a0), "r"(a1), "r"(a2), "r"(a3), "r"(b0), "r"(b1));
}
__device__ __forceinline__ void mma_bf16(
    float& d0, float& d1, float& d2, float& d3,
    uint32_t a0, uint32_t a1, uint32_t a2, uint32_t a3,
    uint32_t b0, uint32_t b1)
{
    asm volatile(
        "mma.sync.aligned.m16n8k16.row.col.f32.bf16.bf16.f32 "
        "{%0,%1,%2,%3}, {%4,%5,%6,%7}, {%8,%9}, {%0,%1,%2,%3};"
        : "+f"(d0), "+f"(d1), "+f"(d2), "+f"(d3)
        : "r"(a0), "r"(a1), "r"(a2), "r"(a3), "r"(b0), "r"(b1));
}
#define CP16(dst_u32, src_ptr) \
    asm volatile("cp.async.cg.shared.global [%0], [%1], 16;" \
                 :: "r"(dst_u32), "l"(src_ptr))

// ---------------------------------------------------------------------------
// K1/K4: tf32 tensor-core GEMM + BN, cp.async 3-stage pipeline.
// out[b,o,n] = BN( sum_c W[o,c] X[b,c,n] ), K=256, N=1024.
// CTA tile 128x128, 8 warps (2x4), warp tile 64x32.
// smem: fp32 tiles; tf32 rounding happens at fragment-load time.
// ---------------------------------------------------------------------------
#define GASTR 20            // A row stride (floats), 80B (16B-aligned)
#define GBSTR 132           // B row stride (floats), 528B (16B-aligned)
#define G_AOFF 0
#define G_BOFF (128 * GASTR)                 // 2560 floats
#define G_STG  (G_BOFF + 16 * GBSTR)         // 4672 floats per stage
#define G_SMEM_BYTES (3 * G_STG * 4)         // 56064 B

__global__ __launch_bounds__(256, 2) void gemm_bn_tc(
    const float* __restrict__ X, const float* __restrict__ W,
    const float* __restrict__ gam, const float* __restrict__ bet,
    const float* __restrict__ mu, const float* __restrict__ va,
    float* __restrict__ out, int M)
{
    extern __shared__ float sm[];

    int b  = blockIdx.z;
    int o0 = blockIdx.y * 128;
    int n0 = blockIdx.x * 128;

    int tid = threadIdx.x, warp = tid >> 5, lane = tid & 31;
    int qr = lane >> 2, qc = lane & 3;
    int wm = (warp >> 2) * 64, wn = (warp & 3) * 32;

    const float* Xb = X + (size_t)b * 256 * NTOK;

    float C[4][4][4];
    #pragma unroll
    for (int i = 0; i < 4; i++)
        #pragma unroll
        for (int j = 0; j < 4; j++)
            #pragma unroll
            for (int r = 0; r < 4; r++) C[i][j][r] = 0.f;

    // load mappings
    int arow = tid >> 1, acol = (tid & 1) * 8;   // A: 128 rows x 16 cols
    int bkr  = tid >> 4, bnc  = (tid & 15) * 8;  // B: 16 rows x 128 cols

    uint32_t smem_u32 = (uint32_t)__cvta_generic_to_shared(sm);
    uint32_t a_dst0 = smem_u32 + (G_AOFF + arow * GASTR + acol) * 4;
    uint32_t b_dst0 = smem_u32 + (G_BOFF + bkr * GBSTR + bnc) * 4;
    const float* a_src0 = W + (o0 + arow) * 256 + acol;
    const float* b_src0 = Xb + bkr * NTOK + n0 + bnc;

    // prologue: issue chunks 0,1 into stages 0,1
    #pragma unroll
    for (int p = 0; p < 2; p++) {
        uint32_t ad = a_dst0 + p * G_STG * 4;
        const float* as = a_src0 + p * 16;
        CP16(ad, as); CP16(ad + 16, as + 4);
        uint32_t bd = b_dst0 + p * G_STG * 4;
        const float* bs = b_src0 + p * 16 * NTOK;
        CP16(bd, bs); CP16(bd + 16, bs + 4);
        asm volatile("cp.async.commit_group;");
    }

    for (int kc = 0; kc < 16; kc++) {
        asm volatile("cp.async.wait_group 1;");
        __syncthreads();

        // prefetch chunk kc+2 into stage (kc+2)%3 (consumed at kc-1, safe)
        if (kc + 2 < 16) {
            int buf = (kc + 2) % 3;
            uint32_t ad = a_dst0 + buf * G_STG * 4;
            const float* as = a_src0 + (kc + 2) * 16;
            CP16(ad, as); CP16(ad + 16, as + 4);
            uint32_t bd = b_dst0 + buf * G_STG * 4;
            const float* bs = b_src0 + (size_t)(kc + 2) * 16 * NTOK;
            CP16(bd, bs); CP16(bd + 16, bs + 4);
        }
        asm volatile("cp.async.commit_group;");

        const float* Ab = sm + (kc % 3) * G_STG;
        const float* Bb = Ab + G_BOFF;

        #pragma unroll
        for (int ks = 0; ks < 2; ks++) {
            int kk = ks * 8;
            uint32_t af[4][4];
            #pragma unroll
            for (int mt = 0; mt < 4; mt++) {
                int r = wm + mt * 16 + qr;
                af[mt][0] = tf32u(Ab[r * GASTR + kk + qc]);
                af[mt][1] = tf32u(Ab[(r + 8) * GASTR + kk + qc]);
                af[mt][2] = tf32u(Ab[r * GASTR + kk + qc + 4]);
                af[mt][3] = tf32u(Ab[(r + 8) * GASTR + kk + qc + 4]);
            }
            uint32_t bfr[4][2];
            #pragma unroll
            for (int nt = 0; nt < 4; nt++) {
                bfr[nt][0] = tf32u(Bb[(kk + qc) * GBSTR + wn + nt * 8 + qr]);
                bfr[nt][1] = tf32u(Bb[(kk + qc + 4) * GBSTR + wn + nt * 8 + qr]);
            }
            #pragma unroll
            for (int mt = 0; mt < 4; mt++)
                #pragma unroll
                for (int nt = 0; nt < 4; nt++)
                    mma_tf32(C[mt][nt][0], C[mt][nt][1], C[mt][nt][2], C[mt][nt][3],
                             af[mt][0], af[mt][1], af[mt][2], af[mt][3],
                             bfr[nt][0], bfr[nt][1]);
        }
    }

    // epilogue: BN + store
    #pragma unroll
    for (int mt = 0; mt < 4; mt++) {
        int r_lo = o0 + wm + mt * 16 + qr;
        int r_hi = r_lo + 8;
        float inv0 = gam[r_lo] * rsqrtf(va[r_lo] + BN_EPS);
        float sh0  = bet[r_lo] - mu[r_lo] * inv0;
        float inv1 = gam[r_hi] * rsqrtf(va[r_hi] + BN_EPS);
        float sh1  = bet[r_hi] - mu[r_hi] * inv1;
        #pragma unroll
        for (int nt = 0; nt < 4; nt++) {
            int col = n0 + wn + nt * 8 + 2 * qc;
            *(float2*)&out[((size_t)b * M + r_lo) * NTOK + col] =
                make_float2(C[mt][nt][0] * inv0 + sh0, C[mt][nt][1] * inv0 + sh0);
            *(float2*)&out[((size_t)b * M + r_hi) * NTOK + col] =
                make_float2(C[mt][nt][2] * inv1 + sh1, C[mt][nt][3] * inv1 + sh1);
        }
    }
}

// ---------------------------------------------------------------------------
// K2: register-resident flash attention, 64-key tiles, 2 CTAs/SM,
// fused dwconv3x3 pos-enc epilogue. (unchanged from round 7)
// ---------------------------------------------------------------------------
#define QSTR 21
#define KSTR2 72
#define VSTR2 36
#define KBUF2 (16 * KSTR2)
#define VBUF2 (32 * VSTR2)
#define BUFSZ2 (KBUF2 + VBUF2)
#define S_TOTAL2 11104

__global__ __launch_bounds__(256, 2) void attn_kernel(
    const float* __restrict__ qkv, float* __restrict__ vattn,
    const float* __restrict__ pe_w,
    const float* __restrict__ pe_g, const float* __restrict__ pe_b,
    const float* __restrict__ pe_m, const float* __restrict__ pe_v)
{
    __shared__ __align__(16) float s_all[S_TOTAL2];
    float* s_q   = s_all;
    float* s_buf = s_all + 128 * QSTR;

    int tid  = threadIdx.x;
    int b    = blockIdx.z, h = blockIdx.y;
    int m0   = blockIdx.x * 128;

    int warp = tid >> 5, lane = tid & 31;
    int qr = lane >> 2;
    int qc = lane & 3;
    int mw = warp * 16;

    const float* base = qkv + ((size_t)b * QKV_OUT + h * 64) * NTOK;

    const float qsc = SCALE_F * LOG2E;
    for (int i = tid; i < 16 * 128; i += 256) {
        int d = i >> 7, mm = i & 127;
        s_q[mm * QSTR + d] = tf32r(base[d * NTOK + m0 + mm] * qsc);
    }
    __syncthreads();

    uint32_t aq[2][4];
    #pragma unroll
    for (int kk = 0; kk < 2; kk++) {
        aq[kk][0] = __float_as_uint(s_q[(mw + qr)     * QSTR + kk * 8 + qc]);
        aq[kk][1] = __float_as_uint(s_q[(mw + qr + 8) * QSTR + kk * 8 + qc]);
        aq[kk][2] = __float_as_uint(s_q[(mw + qr)     * QSTR + kk * 8 + qc + 4]);
        aq[kk][3] = __float_as_uint(s_q[(mw + qr + 8) * QSTR + kk * 8 + qc + 4]);
    }

    float om0 = -1e30f, om1 = -1e30f;
    float rs0 = 0.f, rs1 = 0.f;
    float O[4][4];
    #pragma unroll
    for (int i = 0; i < 4; i++)
        #pragma unroll
        for (int j = 0; j < 4; j++) O[i][j] = 0.f;

    float    kst[4];
    uint32_t vstg[4];

    int kd = tid >> 4;
    int kn4 = (tid & 15) * 4;

    {
        float4 t = *(const float4*)&base[(16 + kd) * NTOK + kn4];
        kst[0] = tf32r(t.x); kst[1] = tf32r(t.y);
        kst[2] = tf32r(t.z); kst[3] = tf32r(t.w);
        #pragma unroll
        for (int j = 0; j < 2; j++) {
            int lin = tid + j * 256;
            int d = lin >> 4, n4 = (lin & 15) * 4;
            float4 v = *(const float4*)&base[(32 + d) * NTOK + n4];
            vstg[2*j]   = pk2(v.x, v.y);
            vstg[2*j+1] = pk2(v.z, v.w);
        }
    }

    for (int t = 0; t < 16; t++) {
        float*    kf = s_buf + (t & 1) * BUFSZ2;
        uint32_t* vw = (uint32_t*)(kf + KBUF2);
        *(float4*)&kf[kd * KSTR2 + kn4] =
            make_float4(kst[0], kst[1], kst[2], kst[3]);
        #pragma unroll
        for (int j = 0; j < 2; j++) {
            int lin = tid + j * 256;
            int d = lin >> 4, n4 = (lin & 15) * 4;
            *(uint2*)&vw[d * VSTR2 + (n4 >> 1)] = make_uint2(vstg[2*j], vstg[2*j+1]);
        }
        __syncthreads();

        if (t < 15) {
            int n0 = (t + 1) * 64;
            float4 tt = *(const float4*)&base[(16 + kd) * NTOK + n0 + kn4];
            kst[0] = tf32r(tt.x); kst[1] = tf32r(tt.y);
            kst[2] = tf32r(tt.z); kst[3] = tf32r(tt.w);
            #pragma unroll
            for (int j = 0; j < 2; j++) {
                int lin = tid + j * 256;
                int d = lin >> 4, n4 = (lin & 15) * 4;
                float4 v = *(const float4*)&base[(32 + d) * NTOK + n0 + n4];
                vstg[2*j]   = pk2(v.x, v.y);
                vstg[2*j+1] = pk2(v.z, v.w);
            }
        }

        float S[8][4];
        #pragma unroll
        for (int nt = 0; nt < 8; nt++) {
            float d0 = 0.f, d1 = 0.f, d2 = 0.f, d3 = 0.f;
            #pragma unroll
            for (int kk = 0; kk < 2; kk++) {
                uint32_t b0 = __float_as_uint(kf[(kk*8 + qc)     * KSTR2 + nt*8 + qr]);
                uint32_t b1 = __float_as_uint(kf[(kk*8 + qc + 4) * KSTR2 + nt*8 + qr]);
                mma_tf32(d0, d1, d2, d3,
                         aq[kk][0], aq[kk][1], aq[kk][2], aq[kk][3], b0, b1);
            }
            S[nt][0] = d0; S[nt][1] = d1; S[nt][2] = d2; S[nt][3] = d3;
        }

        float tm0 = -1e30f, tm1 = -1e30f;
        #pragma unroll
        for (int nt = 0; nt < 8; nt++) {
            tm0 = fmaxf(tm0, fmaxf(S[nt][0], S[nt][1]));
            tm1 = fmaxf(tm1, fmaxf(S[nt][2], S[nt][3]));
        }
        tm0 = fmaxf(tm0, __shfl_xor_sync(0xffffffffu, tm0, 1));
        tm0 = fmaxf(tm0, __shfl_xor_sync(0xffffffffu, tm0, 2));
        tm1 = fmaxf(tm1, __shfl_xor_sync(0xffffffffu, tm1, 1));
        tm1 = fmaxf(tm1, __shfl_xor_sync(0xffffffffu, tm1, 2));

        float nm0 = fmaxf(om0, tm0), nm1 = fmaxf(om1, tm1);
        float f0 = fex2(om0 - nm0),  f1 = fex2(om1 - nm1);
        om0 = nm0; om1 = nm1;

        float ps0 = 0.f, ps1 = 0.f;
        #pragma unroll
        for (int nt = 0; nt < 8; nt++) {
            float e0 = fex2(S[nt][0] - nm0);
            float e1 = fex2(S[nt][1] - nm0);
            float e2 = fex2(S[nt][2] - nm1);
            float e3 = fex2(S[nt][3] - nm1);
            S[nt][0] = e0; S[nt][1] = e1; S[nt][2] = e2; S[nt][3] = e3;
            ps0 += e0 + e1; ps1 += e2 + e3;
        }
        rs0 = rs0 * f0 + ps0;
        rs1 = rs1 * f1 + ps1;
        #pragma unroll
        for (int dt = 0; dt < 4; dt++) {
            O[dt][0] *= f0; O[dt][1] *= f0;
            O[dt][2] *= f1; O[dt][3] *= f1;
        }

        #pragma unroll
        for (int kt = 0; kt < 4; kt++) {
            uint32_t a0 = pk2(S[2*kt][0],   S[2*kt][1]);
            uint32_t a1 = pk2(S[2*kt][2],   S[2*kt][3]);
            uint32_t a2 = pk2(S[2*kt+1][0], S[2*kt+1][1]);
            uint32_t a3 = pk2(S[2*kt+1][2], S[2*kt+1][3]);
            #pragma unroll
            for (int dt = 0; dt < 4; dt++) {
                uint32_t b0 = vw[(dt*8 + qr) * VSTR2 + kt*8 + qc];
                uint32_t b1 = vw[(dt*8 + qr) * VSTR2 + kt*8 + qc + 4];
                mma_bf16(O[dt][0], O[dt][1], O[dt][2], O[dt][3],
                         a0, a1, a2, a3, b0, b1);
            }
        }
    }
    __syncthreads();

    rs0 += __shfl_xor_sync(0xffffffffu, rs0, 1);
    rs0 += __shfl_xor_sync(0xffffffffu, rs0, 2);
    rs1 += __shfl_xor_sync(0xffffffffu, rs1, 1);
    rs1 += __shfl_xor_sync(0xffffffffu, rs1, 2);
    float inv0 = 1.0f / rs0, inv1 = 1.0f / rs1;

    float* ob   = s_all;
    float* pv   = s_all + 4224;
    float* pwb  = s_all + 10752;
    float* pinv = s_all + 11040;
    float* psh  = s_all + 11072;

    #pragma unroll
    for (int dt = 0; dt < 4; dt++) {
        ob[(mw + qr)     * 33 + dt*8 + 2*qc]     = O[dt][0] * inv0;
        ob[(mw + qr)     * 33 + dt*8 + 2*qc + 1] = O[dt][1] * inv0;
        ob[(mw + qr + 8) * 33 + dt*8 + 2*qc]     = O[dt][2] * inv1;
        ob[(mw + qr + 8) * 33 + dt*8 + 2*qc + 1] = O[dt][3] * inv1;
    }

    {
        int r0 = blockIdx.x * 4;
        const float* vbase = base + 32 * NTOK;
        for (int i = tid; i < 32 * 6 * 34; i += 256) {
            int d  = i / 204;
            int rm = i % 204;
            int yy = rm / 34;
            int xx = rm % 34;
            int x  = xx - 1;
            int ry = r0 - 1 + yy;
            float val = 0.f;
            if ((unsigned)x < 32u && (unsigned)ry < 32u)
                val = vbase[d * NTOK + ry * 32 + x];
            pv[i] = val;
        }
        for (int i = tid; i < 288; i += 256)
            pwb[i] = pe_w[h * 32 * 9 + i];
        if (tid < 32) {
            int c = h * 32 + tid;
            float iv = pe_g[c] * rsqrtf(pe_v[c] + BN_EPS);
            pinv[tid] = iv;
            psh[tid]  = pe_b[c] - pe_m[c] * iv;
        }
    }
    __syncthreads();

    float* outp = vattn + ((size_t)b * DIM + h * HEAD_DIM) * NTOK + m0;
    for (int i = tid; i < 32 * 128; i += 256) {
        int d = i >> 7, mm = i & 127;
        int y = mm >> 5, x = mm & 31;
        const float* wd = &pwb[d * 9];
        const float* p0 = &pv[d * 204 + y * 34 + x];
        float pe = wd[0]*p0[0]  + wd[1]*p0[1]  + wd[2]*p0[2]
                 + wd[3]*p0[34] + wd[4]*p0[35] + wd[5]*p0[36]
                 + wd[6]*p0[68] + wd[7]*p0[69] + wd[8]*p0[70];
        outp[d * NTOK + mm] = ob[mm * 33 + d] + pe * pinv[d] + psh[d];
    }
}

// ---------------------------------------------------------------------------
extern "C" void kernel_launch(void* const* d_in, const int* in_sizes, int n_in,
                              void* d_out, int out_size)
{
    const float* x        = (const float*)d_in[0];
    const float* qkv_w    = (const float*)d_in[1];
    const float* qkv_g    = (const float*)d_in[2];
    const float* qkv_b    = (const float*)d_in[3];
    const float* qkv_m    = (const float*)d_in[4];
    const float* qkv_v    = (const float*)d_in[5];
    const float* pe_w     = (const float*)d_in[6];
    const float* pe_g     = (const float*)d_in[7];
    const float* pe_b     = (const float*)d_in[8];
    const float* pe_m     = (const float*)d_in[9];
    const float* pe_v     = (const float*)d_in[10];
    const float* proj_w   = (const float*)d_in[11];
    const float* proj_g   = (const float*)d_in[12];
    const float* proj_b   = (const float*)d_in[13];
    const float* proj_m   = (const float*)d_in[14];
    const float* proj_v   = (const float*)d_in[15];
    float* out            = (float*)d_out;

    float *qkv_ptr, *vattn_ptr;
    cudaGetSymbolAddress((void**)&qkv_ptr, g_qkv);
    cudaGetSymbolAddress((void**)&vattn_ptr, g_vattn);

    cudaFuncSetAttribute(gemm_bn_tc,
        cudaFuncAttributeMaxDynamicSharedMemorySize, G_SMEM_BYTES);

    // K1: qkv = BN(conv1x1(x))  — tf32 tc + cp.async pipeline
    gemm_bn_tc<<<dim3(8, 4, BATCH), 256, G_SMEM_BYTES>>>(
        x, qkv_w, qkv_g, qkv_b, qkv_m, qkv_v, qkv_ptr, QKV_OUT);

    // K2: attention + fused pos-enc -> g_vattn
    attn_kernel<<<dim3(8, NHEADS, BATCH), 256>>>(
        qkv_ptr, vattn_ptr, pe_w, pe_g, pe_b, pe_m, pe_v);

    // K4: out = BN(conv1x1(vattn))  — tf32 tc + cp.async pipeline
    gemm_bn_tc<<<dim3(8, 2, BATCH), 256, G_SMEM_BYTES>>>(
        vattn_ptr, proj_w, proj_g, proj_b, proj_m, proj_v, out, DIM);
}